// round 4
// baseline (speedup 1.0000x reference)
#include <cuda_runtime.h>
#include <cstddef>

#define NN 100000
#define NE 3200000
#define NG 256
#define DIN 128
#define DH 64

// ---------------- scratch (device globals; no allocation). float4 => 16B aligned ----------------
__device__ float  g_deg[NN];
__device__ float  g_dinv[NN];
__device__ int    g_src[NE];
__device__ int    g_dst[NE];
__device__ float  g_ew[NE];
__device__ int    g_batch[NN];
__device__ int    g_flags[2];   // [0]: edge_index is int64, [1]: batch is int64
__device__ float4 g_tx1[(size_t)NN * DIN / 4];
__device__ float4 g_tx2[(size_t)NN * DIN / 4];
__device__ float4 g_h1[(size_t)NN * DH / 4];
__device__ float4 g_tb1[(size_t)NN * DH / 4];
__device__ float4 g_tb2[(size_t)NN * DH / 4];
__device__ float4 g_h2[(size_t)NN * DH / 4];
__device__ float  g_gsum[NG * DH];
__device__ float  g_gcnt[NG];

// ---------------- dtype probe: int64 data with small values has zero odd words ----------------
__global__ void k_detect(const int* __restrict__ ei_raw, const int* __restrict__ batch_raw) {
    __shared__ int s_ei, s_b;
    int t = threadIdx.x;
    if (t == 0) { s_ei = 0; s_b = 0; }
    __syncthreads();
    int acc_e = 0, acc_b = 0;
    for (int k = t; k < 4096; k += blockDim.x) acc_e |= ei_raw[2 * k + 1];
    for (int k = t; k < 4096; k += blockDim.x) acc_b |= batch_raw[2 * k + 1];
    atomicOr(&s_ei, acc_e);
    atomicOr(&s_b, acc_b);
    __syncthreads();
    if (t == 0) {
        g_flags[0] = (s_ei == 0) ? 1 : 0;  // all-zero odd words => int64
        g_flags[1] = (s_b == 0) ? 1 : 0;
    }
}

// ---------------- small utility kernels ----------------
__global__ void k_zero_small() {
    int i = blockIdx.x * blockDim.x + threadIdx.x;
    if (i < NN) g_deg[i] = 0.f;
    if (i < NG * DH) g_gsum[i] = 0.f;
    if (i < NG) g_gcnt[i] = 0.f;
}

__global__ void k_zero4(float4* __restrict__ p, int n4) {
    int i = blockIdx.x * blockDim.x + threadIdx.x;
    if (i < n4) p[i] = make_float4(0.f, 0.f, 0.f, 0.f);
}

__global__ void k_neg4(const float4* __restrict__ in, float4* __restrict__ out, int n4) {
    int i = blockIdx.x * blockDim.x + threadIdx.x;
    if (i < n4) {
        float4 v = in[i];
        out[i] = make_float4(-v.x, -v.y, -v.z, -v.w);
    }
}

// decode indices (int32 or int64 per flag), clamp, count out-degree on src
__global__ void k_deg_prep(const void* __restrict__ ei_raw) {
    int e = blockIdx.x * blockDim.x + threadIdx.x;
    if (e >= NE) return;
    int s, d;
    if (g_flags[0]) {
        const long long* p = (const long long*)ei_raw;
        s = (int)p[e];
        d = (int)p[NE + e];
    } else {
        const int* p = (const int*)ei_raw;
        s = p[e];
        d = p[NE + e];
    }
    s = min(max(s, 0), NN - 1);
    d = min(max(d, 0), NN - 1);
    g_src[e] = s;
    g_dst[e] = d;
    atomicAdd(&g_deg[s], 1.0f);
}

__global__ void k_batch_prep(const void* __restrict__ batch_raw) {
    int i = blockIdx.x * blockDim.x + threadIdx.x;
    if (i >= NN) return;
    int b;
    if (g_flags[1]) b = (int)((const long long*)batch_raw)[i];
    else            b = ((const int*)batch_raw)[i];
    g_batch[i] = min(max(b, 0), NG - 1);
}

__global__ void k_dinv() {
    int i = blockIdx.x * blockDim.x + threadIdx.x;
    if (i < NN) {
        float d = g_deg[i];
        g_dinv[i] = (d > 0.f) ? rsqrtf(d) : 0.f;
    }
}

__global__ void k_ew() {
    int e = blockIdx.x * blockDim.x + threadIdx.x;
    if (e < NE) g_ew[e] = -g_dinv[g_src[e]] * g_dinv[g_dst[e]];
}

// ---------------- edge scatter (Lhat application) ----------------
__device__ __forceinline__ void red_add_v4(float4* p, float4 v) {
    asm volatile("red.global.add.v4.f32 [%0], {%1, %2, %3, %4};"
                 :: "l"(p), "f"(v.x), "f"(v.y), "f"(v.z), "f"(v.w)
                 : "memory");
}

// D=128: one warp per edge; each lane moves one float4 (32*4 = 128 floats)
__global__ void k_scatter128(const float4* __restrict__ in, float4* __restrict__ out, float scale) {
    int g = blockIdx.x * blockDim.x + threadIdx.x;
    int e = g >> 5;
    if (e >= NE) return;
    float w = g_ew[e] * scale;
    int lane = g & 31;
    int s = g_src[e], d = g_dst[e];
    float4 v = in[(size_t)s * 32 + lane];
    if (w != 0.f)
        red_add_v4(out + (size_t)d * 32 + lane,
                   make_float4(v.x * w, v.y * w, v.z * w, v.w * w));
}

// D=64: one half-warp per edge; each lane moves one float4 (16*4 = 64 floats)
__global__ void k_scatter64(const float4* __restrict__ in, float4* __restrict__ out, float scale) {
    int g = blockIdx.x * blockDim.x + threadIdx.x;
    int e = g >> 4;
    if (e >= NE) return;
    float w = g_ew[e] * scale;
    int lane = g & 15;
    int s = g_src[e], d = g_dst[e];
    float4 v = in[(size_t)s * 16 + lane];
    if (w != 0.f)
        red_add_v4(out + (size_t)d * 16 + lane,
                   make_float4(v.x * w, v.y * w, v.z * w, v.w * w));
}

// ---------------- fused GEMM: C = relu([A0|A1|A2] @ W + b) ----------------
// BM=64, BN=64(=HID), BK=32, 256 threads, each thread a 4x4 microtile.
template <int D>
__global__ void k_gemm(const float* __restrict__ A0, const float* __restrict__ A1,
                       const float* __restrict__ A2, const float* __restrict__ W,
                       const float* __restrict__ bias, float* __restrict__ C) {
    constexpr int KTOT = 3 * D;
    __shared__ float sA[32][68];  // [k][m], padded
    __shared__ float sB[32][64];  // [k][n]
    const int tid = threadIdx.x;
    const int m0 = blockIdx.x * 64;
    const int tx = tid & 15;   // col group
    const int ty = tid >> 4;   // row group

    float acc[4][4];
#pragma unroll
    for (int i = 0; i < 4; i++)
#pragma unroll
        for (int j = 0; j < 4; j++) acc[i][j] = 0.f;

    const int lr = tid >> 3;         // 0..31  (A tile: k rows via lc, m rows via lr)
    const int lc = (tid & 7) << 2;   // 0,4,...,28
    const int lrB = tid >> 4;        // 0..15  (B tile rows)
    const int lcB = (tid & 15) << 2; // 0,4,...,60 (B tile cols, covers all 64)

    for (int k0 = 0; k0 < KTOT; k0 += 32) {
        const float* Asrc = (k0 < D) ? A0 : (k0 < 2 * D ? A1 : A2);
        const int kloc = k0 % D;
#pragma unroll
        for (int rr = 0; rr < 2; rr++) {
            int r = lr + rr * 32;
            int gm = m0 + r;
            float4 v = make_float4(0.f, 0.f, 0.f, 0.f);
            if (gm < NN) v = *(const float4*)(Asrc + (size_t)gm * D + kloc + lc);
            sA[lc + 0][r] = v.x;
            sA[lc + 1][r] = v.y;
            sA[lc + 2][r] = v.z;
            sA[lc + 3][r] = v.w;
        }
        // B tile: 32 rows x 64 cols; 256 threads x 2 float4 = full coverage
#pragma unroll
        for (int rr = 0; rr < 2; rr++) {
            int row = lrB + rr * 16;
            float4 w4 = *(const float4*)(W + (size_t)(k0 + row) * 64 + lcB);
            sB[row][lcB + 0] = w4.x;
            sB[row][lcB + 1] = w4.y;
            sB[row][lcB + 2] = w4.z;
            sB[row][lcB + 3] = w4.w;
        }
        __syncthreads();
#pragma unroll
        for (int kk = 0; kk < 32; kk++) {
            float a[4], b4[4];
#pragma unroll
            for (int i = 0; i < 4; i++) a[i] = sA[kk][ty * 4 + i];
#pragma unroll
            for (int j = 0; j < 4; j++) b4[j] = sB[kk][tx * 4 + j];
#pragma unroll
            for (int i = 0; i < 4; i++)
#pragma unroll
                for (int j = 0; j < 4; j++) acc[i][j] = fmaf(a[i], b4[j], acc[i][j]);
        }
        __syncthreads();
    }

    float bb[4];
#pragma unroll
    for (int j = 0; j < 4; j++) bb[j] = bias[tx * 4 + j];
#pragma unroll
    for (int i = 0; i < 4; i++) {
        int gm = m0 + ty * 4 + i;
        if (gm < NN) {
            float4 o;
            o.x = fmaxf(acc[i][0] + bb[0], 0.f);
            o.y = fmaxf(acc[i][1] + bb[1], 0.f);
            o.z = fmaxf(acc[i][2] + bb[2], 0.f);
            o.w = fmaxf(acc[i][3] + bb[3], 0.f);
            *(float4*)(C + (size_t)gm * 64 + tx * 4) = o;
        }
    }
}

// ---------------- pooling + FC ----------------
__global__ void k_pool(const float* __restrict__ h) {
    int idx = blockIdx.x * blockDim.x + threadIdx.x;
    if (idx >= NN * DH) return;
    int node = idx >> 6;
    int col = idx & 63;
    int gph = g_batch[node];
    atomicAdd(&g_gsum[gph * 64 + col], h[idx]);
    if (col == 0) atomicAdd(&g_gcnt[gph], 1.0f);
}

__global__ void k_final(const float* __restrict__ Wfc, const float* __restrict__ bfc,
                        float* __restrict__ out) {
    int gph = threadIdx.x;
    if (gph < NG) {
        float c = fmaxf(g_gcnt[gph], 1.0f);
        float s = 0.f;
#pragma unroll
        for (int o = 0; o < 64; o++) s += g_gsum[gph * 64 + o] * Wfc[o];
        out[gph] = s / c + bfc[0];
    }
}

// ---------------- launch ----------------
extern "C" void kernel_launch(void* const* d_in, const int* in_sizes, int n_in,
                              void* d_out, int out_size) {
    // Resolve inputs by element count (robust to metadata ordering).
    // x: 12,800,000 | edge_index: 6,400,000 | batch: 100,000
    // W1: 24,576 | W2: 12,288 | bfc: 1 | {b1, b2, Wfc}: 64 each.
    const float *x = nullptr, *W1 = nullptr, *b1 = nullptr, *W2 = nullptr,
                *b2 = nullptr, *Wfc = nullptr, *bfc = nullptr;
    const void *ei = nullptr, *batch = nullptr;
    int idx64[3] = {-1, -1, -1};
    int n64 = 0, idxW2 = -1;
    for (int i = 0; i < n_in; i++) {
        int s = in_sizes[i];
        switch (s) {
            case 12800000: x = (const float*)d_in[i]; break;
            case 6400000:  ei = d_in[i]; break;
            case 100000:   batch = d_in[i]; break;
            case 24576:    W1 = (const float*)d_in[i]; break;
            case 12288:    W2 = (const float*)d_in[i]; idxW2 = i; break;
            case 1:        bfc = (const float*)d_in[i]; break;
            case 64:       if (n64 < 3) idx64[n64++] = i; break;
            default: break;
        }
    }
    // Disambiguate the three 64-element vectors by position relative to W2:
    // dict order (x, ei, batch, W1, b1, W2, b2, Wfc, bfc): first 64 precedes W2 -> b1, b2, Wfc
    // alphabetical (W1, W2, Wfc, b1, b2, ...): first 64 follows W2 -> Wfc, b1, b2
    if (n64 == 3) {
        if (idx64[0] < idxW2) {
            b1 = (const float*)d_in[idx64[0]];
            b2 = (const float*)d_in[idx64[1]];
            Wfc = (const float*)d_in[idx64[2]];
        } else {
            Wfc = (const float*)d_in[idx64[0]];
            b1 = (const float*)d_in[idx64[1]];
            b2 = (const float*)d_in[idx64[2]];
        }
    }
    float* out = (float*)d_out;

    float4 *tx1, *tx2, *h1, *tb1, *tb2, *h2;
    cudaGetSymbolAddress((void**)&tx1, g_tx1);
    cudaGetSymbolAddress((void**)&tx2, g_tx2);
    cudaGetSymbolAddress((void**)&h1, g_h1);
    cudaGetSymbolAddress((void**)&tb1, g_tb1);
    cudaGetSymbolAddress((void**)&tb2, g_tb2);
    cudaGetSymbolAddress((void**)&h2, g_h2);

    const int TB = 256;
    const int n128_4 = NN * DIN / 4;  // 3.2M float4
    const int n64_4 = NN * DH / 4;    // 1.6M float4

    // dtype probe + prep: degrees, dinv, edge weights, int32 indices
    k_detect<<<1, 256>>>((const int*)ei, (const int*)batch);
    k_zero_small<<<(NN + TB - 1) / TB, TB>>>();
    k_deg_prep<<<(NE + TB - 1) / TB, TB>>>(ei);
    k_batch_prep<<<(NN + TB - 1) / TB, TB>>>(batch);
    k_dinv<<<(NN + TB - 1) / TB, TB>>>();
    k_ew<<<(NE + TB - 1) / TB, TB>>>();

    // layer 1: Tx1 = Lhat(x); Tx2 = 2*Lhat(Tx1) - x  (Tx2 pre-init to -x)
    k_zero4<<<(n128_4 + TB - 1) / TB, TB>>>(tx1, n128_4);
    k_neg4<<<(n128_4 + TB - 1) / TB, TB>>>((const float4*)x, tx2, n128_4);
    {
        long long t = (long long)NE * 32;
        k_scatter128<<<(int)((t + TB - 1) / TB), TB>>>((const float4*)x, tx1, 1.0f);
        k_scatter128<<<(int)((t + TB - 1) / TB), TB>>>(tx1, tx2, 2.0f);
    }
    k_gemm<DIN><<<(NN + 63) / 64, TB>>>(x, (const float*)tx1, (const float*)tx2, W1, b1, (float*)h1);

    // layer 2
    k_zero4<<<(n64_4 + TB - 1) / TB, TB>>>(tb1, n64_4);
    k_neg4<<<(n64_4 + TB - 1) / TB, TB>>>((const float4*)h1, tb2, n64_4);
    {
        long long t = (long long)NE * 16;
        k_scatter64<<<(int)((t + TB - 1) / TB), TB>>>((const float4*)h1, tb1, 1.0f);
        k_scatter64<<<(int)((t + TB - 1) / TB), TB>>>(tb1, tb2, 2.0f);
    }
    k_gemm<DH><<<(NN + 63) / 64, TB>>>((const float*)h1, (const float*)tb1, (const float*)tb2, W2, b2, (float*)h2);

    // mean pool per graph + FC
    k_pool<<<(NN * DH + TB - 1) / TB, TB>>>((const float*)h2);
    k_final<<<1, TB>>>(Wfc, bfc, out);
}

// round 5
// speedup vs baseline: 2.5819x; 2.5819x over previous
#include <cuda_runtime.h>
#include <cstddef>

#define NN 100000
#define NE 3200000
#define NG 256
#define DIN 128
#define DH 64

// ---------------- scratch (device globals; no allocation) ----------------
__device__ float  g_deg[NN];
__device__ float  g_dinv[NN];
__device__ int    g_src[NE];
__device__ int    g_dst[NE];
__device__ int    g_indeg[NN];
__device__ int    g_rowstart[NN];
__device__ int    g_fill[NN];
__device__ int    g_alloc;
__device__ int2   g_csr[NE];          // {src, bitcast(weight)}
__device__ int    g_batch[NN];
__device__ int    g_flags[2];         // [0]: edge_index is int64, [1]: batch is int64
__device__ float4 g_tx1[(size_t)NN * DIN / 4];
__device__ float4 g_tx2[(size_t)NN * DIN / 4];
__device__ float4 g_h1[(size_t)NN * DH / 4];
__device__ float4 g_tb1[(size_t)NN * DH / 4];
__device__ float4 g_tb2[(size_t)NN * DH / 4];
__device__ float4 g_h2[(size_t)NN * DH / 4];
__device__ float  g_gsum[NG * DH];
__device__ float  g_gcnt[NG];

// ---------------- dtype probe: int64 data with small values has zero odd words ----------------
__global__ void k_detect(const int* __restrict__ ei_raw, const int* __restrict__ batch_raw) {
    __shared__ int s_ei, s_b;
    int t = threadIdx.x;
    if (t == 0) { s_ei = 0; s_b = 0; }
    __syncthreads();
    int acc_e = 0, acc_b = 0;
    for (int k = t; k < 4096; k += blockDim.x) acc_e |= ei_raw[2 * k + 1];
    for (int k = t; k < 4096; k += blockDim.x) acc_b |= batch_raw[2 * k + 1];
    atomicOr(&s_ei, acc_e);
    atomicOr(&s_b, acc_b);
    __syncthreads();
    if (t == 0) {
        g_flags[0] = (s_ei == 0) ? 1 : 0;
        g_flags[1] = (s_b == 0) ? 1 : 0;
    }
}

// ---------------- prep ----------------
__global__ void k_zero_small() {
    int i = blockIdx.x * blockDim.x + threadIdx.x;
    if (i < NN) { g_deg[i] = 0.f; g_indeg[i] = 0; g_fill[i] = 0; }
    if (i < NG * DH) g_gsum[i] = 0.f;
    if (i < NG) g_gcnt[i] = 0.f;
    if (i == 0) g_alloc = 0;
}

// decode indices, clamp, count src out-degree (float) and dst in-degree (int)
__global__ void k_deg_prep(const void* __restrict__ ei_raw) {
    int e = blockIdx.x * blockDim.x + threadIdx.x;
    if (e >= NE) return;
    int s, d;
    if (g_flags[0]) {
        const long long* p = (const long long*)ei_raw;
        s = (int)p[e];
        d = (int)p[NE + e];
    } else {
        const int* p = (const int*)ei_raw;
        s = p[e];
        d = p[NE + e];
    }
    s = min(max(s, 0), NN - 1);
    d = min(max(d, 0), NN - 1);
    g_src[e] = s;
    g_dst[e] = d;
    atomicAdd(&g_deg[s], 1.0f);
    atomicAdd(&g_indeg[d], 1);
}

__global__ void k_batch_prep(const void* __restrict__ batch_raw) {
    int i = blockIdx.x * blockDim.x + threadIdx.x;
    if (i >= NN) return;
    int b;
    if (g_flags[1]) b = (int)((const long long*)batch_raw)[i];
    else            b = ((const int*)batch_raw)[i];
    g_batch[i] = min(max(b, 0), NG - 1);
}

__global__ void k_dinv() {
    int i = blockIdx.x * blockDim.x + threadIdx.x;
    if (i < NN) {
        float d = g_deg[i];
        g_dinv[i] = (d > 0.f) ? rsqrtf(d) : 0.f;
    }
}

// CSR row allocation: warp-scan of in-degrees, one atomicAdd per warp
__global__ void k_alloc() {
    int i = blockIdx.x * blockDim.x + threadIdx.x;
    int lane = threadIdx.x & 31;
    int v = (i < NN) ? g_indeg[i] : 0;
    int s = v;
#pragma unroll
    for (int o = 1; o < 32; o <<= 1) {
        int t = __shfl_up_sync(0xFFFFFFFF, s, o);
        if (lane >= o) s += t;
    }
    int total = __shfl_sync(0xFFFFFFFF, s, 31);
    int base = 0;
    if (lane == 31) base = atomicAdd(&g_alloc, total);
    base = __shfl_sync(0xFFFFFFFF, base, 31);
    if (i < NN) g_rowstart[i] = base + s - v;
}

// fill CSR; weight computed inline: w = -dinv[src]*dinv[dst]
__global__ void k_fill() {
    int e = blockIdx.x * blockDim.x + threadIdx.x;
    if (e >= NE) return;
    int s = g_src[e], d = g_dst[e];
    float w = -g_dinv[s] * g_dinv[d];
    int pos = atomicAdd(&g_fill[d], 1);
    int2 ent;
    ent.x = s;
    ent.y = __float_as_int(w);
    g_csr[g_rowstart[d] + pos] = ent;
}

// ---------------- gather (Lhat application), CSR by dst ----------------
// D=128: one warp per dst node; each lane owns one float4 column chunk.
// acc init: 0 (subsrc==nullptr) or -subsrc[node] (folds Tx2 = 2*Lhat(Tx1) - x).
__global__ void k_gather128(const float4* __restrict__ in, float4* __restrict__ out,
                            const float4* __restrict__ subsrc, float scale) {
    int g = blockIdx.x * blockDim.x + threadIdx.x;
    int node = g >> 5;
    if (node >= NN) return;
    int lane = g & 31;
    int start = g_rowstart[node];
    int cnt = g_indeg[node];
    float4 acc;
    if (subsrc) {
        float4 t = subsrc[(size_t)node * 32 + lane];
        acc = make_float4(-t.x, -t.y, -t.z, -t.w);
    } else {
        acc = make_float4(0.f, 0.f, 0.f, 0.f);
    }
    const int2* cs = g_csr + start;
    int j = 0;
    for (; j + 4 <= cnt; j += 4) {
        int2 e0 = cs[j], e1 = cs[j + 1], e2 = cs[j + 2], e3 = cs[j + 3];
        float4 v0 = in[(size_t)e0.x * 32 + lane];
        float4 v1 = in[(size_t)e1.x * 32 + lane];
        float4 v2 = in[(size_t)e2.x * 32 + lane];
        float4 v3 = in[(size_t)e3.x * 32 + lane];
        float w0 = __int_as_float(e0.y) * scale;
        float w1 = __int_as_float(e1.y) * scale;
        float w2 = __int_as_float(e2.y) * scale;
        float w3 = __int_as_float(e3.y) * scale;
        acc.x += w0 * v0.x + w1 * v1.x + w2 * v2.x + w3 * v3.x;
        acc.y += w0 * v0.y + w1 * v1.y + w2 * v2.y + w3 * v3.y;
        acc.z += w0 * v0.z + w1 * v1.z + w2 * v2.z + w3 * v3.z;
        acc.w += w0 * v0.w + w1 * v1.w + w2 * v2.w + w3 * v3.w;
    }
    for (; j < cnt; j++) {
        int2 e0 = cs[j];
        float4 v0 = in[(size_t)e0.x * 32 + lane];
        float w0 = __int_as_float(e0.y) * scale;
        acc.x += w0 * v0.x;
        acc.y += w0 * v0.y;
        acc.z += w0 * v0.z;
        acc.w += w0 * v0.w;
    }
    out[(size_t)node * 32 + lane] = acc;
}

// D=64: one half-warp (16 lanes) per dst node; each lane owns one float4 chunk.
__global__ void k_gather64(const float4* __restrict__ in, float4* __restrict__ out,
                           const float4* __restrict__ subsrc, float scale) {
    int g = blockIdx.x * blockDim.x + threadIdx.x;
    int node = g >> 4;
    if (node >= NN) return;
    int lane = g & 15;
    int start = g_rowstart[node];
    int cnt = g_indeg[node];
    float4 acc;
    if (subsrc) {
        float4 t = subsrc[(size_t)node * 16 + lane];
        acc = make_float4(-t.x, -t.y, -t.z, -t.w);
    } else {
        acc = make_float4(0.f, 0.f, 0.f, 0.f);
    }
    const int2* cs = g_csr + start;
    int j = 0;
    for (; j + 4 <= cnt; j += 4) {
        int2 e0 = cs[j], e1 = cs[j + 1], e2 = cs[j + 2], e3 = cs[j + 3];
        float4 v0 = in[(size_t)e0.x * 16 + lane];
        float4 v1 = in[(size_t)e1.x * 16 + lane];
        float4 v2 = in[(size_t)e2.x * 16 + lane];
        float4 v3 = in[(size_t)e3.x * 16 + lane];
        float w0 = __int_as_float(e0.y) * scale;
        float w1 = __int_as_float(e1.y) * scale;
        float w2 = __int_as_float(e2.y) * scale;
        float w3 = __int_as_float(e3.y) * scale;
        acc.x += w0 * v0.x + w1 * v1.x + w2 * v2.x + w3 * v3.x;
        acc.y += w0 * v0.y + w1 * v1.y + w2 * v2.y + w3 * v3.y;
        acc.z += w0 * v0.z + w1 * v1.z + w2 * v2.z + w3 * v3.z;
        acc.w += w0 * v0.w + w1 * v1.w + w2 * v2.w + w3 * v3.w;
    }
    for (; j < cnt; j++) {
        int2 e0 = cs[j];
        float4 v0 = in[(size_t)e0.x * 16 + lane];
        float w0 = __int_as_float(e0.y) * scale;
        acc.x += w0 * v0.x;
        acc.y += w0 * v0.y;
        acc.z += w0 * v0.z;
        acc.w += w0 * v0.w;
    }
    out[(size_t)node * 16 + lane] = acc;
}

// ---------------- fused GEMM: C = relu([A0|A1|A2] @ W + b) ----------------
template <int D>
__global__ void k_gemm(const float* __restrict__ A0, const float* __restrict__ A1,
                       const float* __restrict__ A2, const float* __restrict__ W,
                       const float* __restrict__ bias, float* __restrict__ C) {
    constexpr int KTOT = 3 * D;
    __shared__ float sA[32][68];
    __shared__ float sB[32][64];
    const int tid = threadIdx.x;
    const int m0 = blockIdx.x * 64;
    const int tx = tid & 15;
    const int ty = tid >> 4;

    float acc[4][4];
#pragma unroll
    for (int i = 0; i < 4; i++)
#pragma unroll
        for (int j = 0; j < 4; j++) acc[i][j] = 0.f;

    const int lr = tid >> 3;
    const int lc = (tid & 7) << 2;
    const int lrB = tid >> 4;
    const int lcB = (tid & 15) << 2;

    for (int k0 = 0; k0 < KTOT; k0 += 32) {
        const float* Asrc = (k0 < D) ? A0 : (k0 < 2 * D ? A1 : A2);
        const int kloc = k0 % D;
#pragma unroll
        for (int rr = 0; rr < 2; rr++) {
            int r = lr + rr * 32;
            int gm = m0 + r;
            float4 v = make_float4(0.f, 0.f, 0.f, 0.f);
            if (gm < NN) v = *(const float4*)(Asrc + (size_t)gm * D + kloc + lc);
            sA[lc + 0][r] = v.x;
            sA[lc + 1][r] = v.y;
            sA[lc + 2][r] = v.z;
            sA[lc + 3][r] = v.w;
        }
#pragma unroll
        for (int rr = 0; rr < 2; rr++) {
            int row = lrB + rr * 16;
            float4 w4 = *(const float4*)(W + (size_t)(k0 + row) * 64 + lcB);
            sB[row][lcB + 0] = w4.x;
            sB[row][lcB + 1] = w4.y;
            sB[row][lcB + 2] = w4.z;
            sB[row][lcB + 3] = w4.w;
        }
        __syncthreads();
#pragma unroll
        for (int kk = 0; kk < 32; kk++) {
            float a[4], b4[4];
#pragma unroll
            for (int i = 0; i < 4; i++) a[i] = sA[kk][ty * 4 + i];
#pragma unroll
            for (int j = 0; j < 4; j++) b4[j] = sB[kk][tx * 4 + j];
#pragma unroll
            for (int i = 0; i < 4; i++)
#pragma unroll
                for (int j = 0; j < 4; j++) acc[i][j] = fmaf(a[i], b4[j], acc[i][j]);
        }
        __syncthreads();
    }

    float bb[4];
#pragma unroll
    for (int j = 0; j < 4; j++) bb[j] = bias[tx * 4 + j];
#pragma unroll
    for (int i = 0; i < 4; i++) {
        int gm = m0 + ty * 4 + i;
        if (gm < NN) {
            float4 o;
            o.x = fmaxf(acc[i][0] + bb[0], 0.f);
            o.y = fmaxf(acc[i][1] + bb[1], 0.f);
            o.z = fmaxf(acc[i][2] + bb[2], 0.f);
            o.w = fmaxf(acc[i][3] + bb[3], 0.f);
            *(float4*)(C + (size_t)gm * 64 + tx * 4) = o;
        }
    }
}

// ---------------- pooling + FC ----------------
// batch is sorted: accumulate runs in registers, flush on graph change.
// block = 256 threads = 4 node-lanes x 64 cols; block covers 128 nodes.
__global__ void k_pool(const float* __restrict__ h) {
    int col = threadIdx.x & 63;
    int sub = threadIdx.x >> 6;
    int n0 = blockIdx.x * 128 + sub * 32;
    float acc = 0.f;
    int cur = -1;
    for (int k = 0; k < 32; k++) {
        int n = n0 + k;
        if (n >= NN) break;
        int gph = g_batch[n];
        if (gph != cur) {
            if (cur >= 0) atomicAdd(&g_gsum[cur * 64 + col], acc);
            cur = gph;
            acc = 0.f;
        }
        acc += h[(size_t)n * 64 + col];
    }
    if (cur >= 0) atomicAdd(&g_gsum[cur * 64 + col], acc);
}

__global__ void k_count() {
    int i = blockIdx.x * blockDim.x + threadIdx.x;
    if (i < NN) atomicAdd(&g_gcnt[g_batch[i]], 1.0f);
}

__global__ void k_final(const float* __restrict__ Wfc, const float* __restrict__ bfc,
                        float* __restrict__ out) {
    int gph = threadIdx.x;
    if (gph < NG) {
        float c = fmaxf(g_gcnt[gph], 1.0f);
        float s = 0.f;
#pragma unroll
        for (int o = 0; o < 64; o++) s += g_gsum[gph * 64 + o] * Wfc[o];
        out[gph] = s / c + bfc[0];
    }
}

// ---------------- launch ----------------
extern "C" void kernel_launch(void* const* d_in, const int* in_sizes, int n_in,
                              void* d_out, int out_size) {
    const float *x = nullptr, *W1 = nullptr, *b1 = nullptr, *W2 = nullptr,
                *b2 = nullptr, *Wfc = nullptr, *bfc = nullptr;
    const void *ei = nullptr, *batch = nullptr;
    int idx64[3] = {-1, -1, -1};
    int n64 = 0, idxW2 = -1;
    for (int i = 0; i < n_in; i++) {
        int s = in_sizes[i];
        switch (s) {
            case 12800000: x = (const float*)d_in[i]; break;
            case 6400000:  ei = d_in[i]; break;
            case 100000:   batch = d_in[i]; break;
            case 24576:    W1 = (const float*)d_in[i]; break;
            case 12288:    W2 = (const float*)d_in[i]; idxW2 = i; break;
            case 1:        bfc = (const float*)d_in[i]; break;
            case 64:       if (n64 < 3) idx64[n64++] = i; break;
            default: break;
        }
    }
    if (n64 == 3) {
        if (idx64[0] < idxW2) {
            b1 = (const float*)d_in[idx64[0]];
            b2 = (const float*)d_in[idx64[1]];
            Wfc = (const float*)d_in[idx64[2]];
        } else {
            Wfc = (const float*)d_in[idx64[0]];
            b1 = (const float*)d_in[idx64[1]];
            b2 = (const float*)d_in[idx64[2]];
        }
    }
    float* out = (float*)d_out;

    float4 *tx1, *tx2, *h1, *tb1, *tb2, *h2;
    cudaGetSymbolAddress((void**)&tx1, g_tx1);
    cudaGetSymbolAddress((void**)&tx2, g_tx2);
    cudaGetSymbolAddress((void**)&h1, g_h1);
    cudaGetSymbolAddress((void**)&tb1, g_tb1);
    cudaGetSymbolAddress((void**)&tb2, g_tb2);
    cudaGetSymbolAddress((void**)&h2, g_h2);

    const int TB = 256;

    // dtype probe + prep + CSR build
    k_detect<<<1, 256>>>((const int*)ei, (const int*)batch);
    k_zero_small<<<(NN + TB - 1) / TB, TB>>>();
    k_deg_prep<<<(NE + TB - 1) / TB, TB>>>(ei);
    k_batch_prep<<<(NN + TB - 1) / TB, TB>>>(batch);
    k_dinv<<<(NN + TB - 1) / TB, TB>>>();
    k_alloc<<<(NN + TB - 1) / TB, TB>>>();
    k_fill<<<(NE + TB - 1) / TB, TB>>>();

    // layer 1: Tx1 = Lhat(x); Tx2 = 2*Lhat(Tx1) - x
    {
        int g128 = (NN * 32 + TB - 1) / TB;
        k_gather128<<<g128, TB>>>((const float4*)x, tx1, nullptr, 1.0f);
        k_gather128<<<g128, TB>>>(tx1, tx2, (const float4*)x, 2.0f);
    }
    k_gemm<DIN><<<(NN + 63) / 64, TB>>>(x, (const float*)tx1, (const float*)tx2, W1, b1, (float*)h1);

    // layer 2
    {
        int g64 = (NN * 16 + TB - 1) / TB;
        k_gather64<<<g64, TB>>>(h1, tb1, nullptr, 1.0f);
        k_gather64<<<g64, TB>>>(tb1, tb2, h1, 2.0f);
    }
    k_gemm<DH><<<(NN + 63) / 64, TB>>>((const float*)h1, (const float*)tb1, (const float*)tb2, W2, b2, (float*)h2);

    // mean pool per graph + FC
    k_pool<<<(NN + 127) / 128, TB>>>((const float*)h2);
    k_count<<<(NN + TB - 1) / TB, TB>>>();
    k_final<<<1, TB>>>(Wfc, bfc, out);
}

// round 6
// speedup vs baseline: 2.7973x; 1.0834x over previous
#include <cuda_runtime.h>
#include <cstddef>

#define NN 100000
#define NE 3200000
#define NG 256
#define DIN 128
#define DH 64

// ---------------- scratch (device globals; no allocation) ----------------
__device__ float  g_deg[NN];
__device__ float  g_dinv[NN];
__device__ int    g_src[NE];
__device__ int    g_dst[NE];
__device__ int    g_indeg[NN];
__device__ int    g_rowstart[NN];
__device__ int    g_fill[NN];
__device__ int    g_alloc;
__device__ int2   g_csr[NE];          // {src, bitcast(weight)}
__device__ int    g_batch[NN];
__device__ int    g_flags[2];
__device__ float  g_wcat[DIN * 192];  // [W0-W2 | W1 | W2] for layer 1
__device__ float4 g_P[(size_t)NN * 192 / 4];   // x @ wcat
__device__ float4 g_Q[(size_t)NN * DIN / 4];   // Lhat(P[:,64:192])
__device__ float4 g_h1[(size_t)NN * DH / 4];
__device__ float4 g_tb1[(size_t)NN * DH / 4];
__device__ float4 g_tb2[(size_t)NN * DH / 4];
__device__ float4 g_h2[(size_t)NN * DH / 4];
__device__ float  g_gsum[NG * DH];
__device__ float  g_gcnt[NG];

// ---------------- dtype probe ----------------
__global__ void k_detect(const int* __restrict__ ei_raw, const int* __restrict__ batch_raw) {
    __shared__ int s_ei, s_b;
    int t = threadIdx.x;
    if (t == 0) { s_ei = 0; s_b = 0; }
    __syncthreads();
    int acc_e = 0, acc_b = 0;
    for (int k = t; k < 4096; k += blockDim.x) acc_e |= ei_raw[2 * k + 1];
    for (int k = t; k < 4096; k += blockDim.x) acc_b |= batch_raw[2 * k + 1];
    atomicOr(&s_ei, acc_e);
    atomicOr(&s_b, acc_b);
    __syncthreads();
    if (t == 0) {
        g_flags[0] = (s_ei == 0) ? 1 : 0;
        g_flags[1] = (s_b == 0) ? 1 : 0;
    }
}

// ---------------- prep ----------------
__global__ void k_zero_small() {
    int i = blockIdx.x * blockDim.x + threadIdx.x;
    if (i < NN) { g_deg[i] = 0.f; g_indeg[i] = 0; g_fill[i] = 0; }
    if (i < NG * DH) g_gsum[i] = 0.f;
    if (i < NG) g_gcnt[i] = 0.f;
    if (i == 0) g_alloc = 0;
}

// decode 2 edges/thread, clamp, count degrees
__global__ void k_deg_prep(const void* __restrict__ ei_raw) {
    int t = blockIdx.x * blockDim.x + threadIdx.x;
    int e = t * 2;
    if (e >= NE) return;
    int s0, s1, d0, d1;
    if (g_flags[0]) {
        longlong2 sp = ((const longlong2*)ei_raw)[t];
        longlong2 dp = ((const longlong2*)((const long long*)ei_raw + NE))[t];
        s0 = (int)sp.x; s1 = (int)sp.y;
        d0 = (int)dp.x; d1 = (int)dp.y;
    } else {
        int2 sp = ((const int2*)ei_raw)[t];
        int2 dp = ((const int2*)((const int*)ei_raw + NE))[t];
        s0 = sp.x; s1 = sp.y;
        d0 = dp.x; d1 = dp.y;
    }
    s0 = min(max(s0, 0), NN - 1); s1 = min(max(s1, 0), NN - 1);
    d0 = min(max(d0, 0), NN - 1); d1 = min(max(d1, 0), NN - 1);
    g_src[e] = s0; g_src[e + 1] = s1;
    g_dst[e] = d0; g_dst[e + 1] = d1;
    atomicAdd(&g_deg[s0], 1.0f);
    atomicAdd(&g_deg[s1], 1.0f);
    atomicAdd(&g_indeg[d0], 1);
    atomicAdd(&g_indeg[d1], 1);
}

__global__ void k_batch_prep(const void* __restrict__ batch_raw) {
    int i = blockIdx.x * blockDim.x + threadIdx.x;
    if (i >= NN) return;
    int b;
    if (g_flags[1]) b = (int)((const long long*)batch_raw)[i];
    else            b = ((const int*)batch_raw)[i];
    b = min(max(b, 0), NG - 1);
    g_batch[i] = b;
    atomicAdd(&g_gcnt[b], 1.0f);
}

// dinv + CSR row allocation (warp-scan, one atomicAdd per warp)
__global__ void k_alloc() {
    int i = blockIdx.x * blockDim.x + threadIdx.x;
    int lane = threadIdx.x & 31;
    if (i < NN) {
        float d = g_deg[i];
        g_dinv[i] = (d > 0.f) ? rsqrtf(d) : 0.f;
    }
    int v = (i < NN) ? g_indeg[i] : 0;
    int s = v;
#pragma unroll
    for (int o = 1; o < 32; o <<= 1) {
        int t = __shfl_up_sync(0xFFFFFFFF, s, o);
        if (lane >= o) s += t;
    }
    int total = __shfl_sync(0xFFFFFFFF, s, 31);
    int base = 0;
    if (lane == 31) base = atomicAdd(&g_alloc, total);
    base = __shfl_sync(0xFFFFFFFF, base, 31);
    if (i < NN) g_rowstart[i] = base + s - v;
}

__global__ void k_fill() {
    int e = blockIdx.x * blockDim.x + threadIdx.x;
    if (e >= NE) return;
    int s = g_src[e], d = g_dst[e];
    float w = -g_dinv[s] * g_dinv[d];
    int pos = atomicAdd(&g_fill[d], 1);
    int2 ent;
    ent.x = s;
    ent.y = __float_as_int(w);
    g_csr[g_rowstart[d] + pos] = ent;
}

// build Wcat = [W0-W2 | W1 | W2] (128 x 192)
__global__ void k_wcat(const float* __restrict__ W1) {
    int t = blockIdx.x * blockDim.x + threadIdx.x;
    if (t >= DIN * 192) return;
    int i = t / 192, o = t % 192;
    float v;
    if (o < 64)       v = W1[i * 64 + o] - W1[2 * 8192 + i * 64 + o];
    else if (o < 128) v = W1[8192 + i * 64 + (o - 64)];
    else              v = W1[2 * 8192 + i * 64 + (o - 128)];
    g_wcat[t] = v;
}

// ---------------- GEMM: P = x @ Wcat  (N x 128) @ (128 x 192) ----------------
// BM=128, BN=64, BK=32, 256 threads, 8x4 microtile. grid (ceil(N/128), 3)
__global__ void k_gemm_p(const float4* __restrict__ A4, float* __restrict__ C) {
    __shared__ float sA[32][132];
    __shared__ float sB[32][64];
    const int tid = threadIdx.x;
    const int m0 = blockIdx.x * 128;
    const int n0 = blockIdx.y * 64;
    const int tx = tid & 15, ty = tid >> 4;
    const int lrow = tid >> 3, lcol4 = tid & 7;
    const int lrB = tid >> 4, lcB = (tid & 15) << 2;

    float acc[8][4];
#pragma unroll
    for (int i = 0; i < 8; i++)
#pragma unroll
        for (int j = 0; j < 4; j++) acc[i][j] = 0.f;

    for (int k0 = 0; k0 < 128; k0 += 32) {
#pragma unroll
        for (int r = 0; r < 4; r++) {
            int row = lrow + r * 32;
            int gm = m0 + row;
            float4 v = make_float4(0.f, 0.f, 0.f, 0.f);
            if (gm < NN) v = A4[(size_t)gm * 32 + (k0 >> 2) + lcol4];
            sA[lcol4 * 4 + 0][row] = v.x;
            sA[lcol4 * 4 + 1][row] = v.y;
            sA[lcol4 * 4 + 2][row] = v.z;
            sA[lcol4 * 4 + 3][row] = v.w;
        }
#pragma unroll
        for (int rr = 0; rr < 2; rr++) {
            int row = lrB + rr * 16;
            float4 w4 = *(const float4*)(g_wcat + (size_t)(k0 + row) * 192 + n0 + lcB);
            sB[row][lcB + 0] = w4.x;
            sB[row][lcB + 1] = w4.y;
            sB[row][lcB + 2] = w4.z;
            sB[row][lcB + 3] = w4.w;
        }
        __syncthreads();
#pragma unroll
        for (int kk = 0; kk < 32; kk++) {
            float a[8], b[4];
#pragma unroll
            for (int i = 0; i < 8; i++) a[i] = sA[kk][ty * 8 + i];
#pragma unroll
            for (int j = 0; j < 4; j++) b[j] = sB[kk][tx * 4 + j];
#pragma unroll
            for (int i = 0; i < 8; i++)
#pragma unroll
                for (int j = 0; j < 4; j++) acc[i][j] = fmaf(a[i], b[j], acc[i][j]);
        }
        __syncthreads();
    }
#pragma unroll
    for (int i = 0; i < 8; i++) {
        int gm = m0 + ty * 8 + i;
        if (gm < NN)
            *(float4*)(C + (size_t)gm * 192 + n0 + tx * 4) =
                make_float4(acc[i][0], acc[i][1], acc[i][2], acc[i][3]);
    }
}

// ---------------- gathers ----------------
// Q = Lhat(P[:,64:192]): warp per node, src rows stride 48 float4, offset 16
__global__ void k_gather128q(const float4* __restrict__ P4, float4* __restrict__ Q4) {
    int g = blockIdx.x * blockDim.x + threadIdx.x;
    int node = g >> 5;
    if (node >= NN) return;
    int lane = g & 31;
    int start = g_rowstart[node];
    int cnt = g_indeg[node];
    float4 acc = make_float4(0.f, 0.f, 0.f, 0.f);
    const int2* cs = g_csr + start;
    int j = 0;
    for (; j + 4 <= cnt; j += 4) {
        int2 e0 = cs[j], e1 = cs[j + 1], e2 = cs[j + 2], e3 = cs[j + 3];
        float4 v0 = P4[(size_t)e0.x * 48 + 16 + lane];
        float4 v1 = P4[(size_t)e1.x * 48 + 16 + lane];
        float4 v2 = P4[(size_t)e2.x * 48 + 16 + lane];
        float4 v3 = P4[(size_t)e3.x * 48 + 16 + lane];
        float w0 = __int_as_float(e0.y), w1 = __int_as_float(e1.y);
        float w2 = __int_as_float(e2.y), w3 = __int_as_float(e3.y);
        acc.x += w0 * v0.x + w1 * v1.x + w2 * v2.x + w3 * v3.x;
        acc.y += w0 * v0.y + w1 * v1.y + w2 * v2.y + w3 * v3.y;
        acc.z += w0 * v0.z + w1 * v1.z + w2 * v2.z + w3 * v3.z;
        acc.w += w0 * v0.w + w1 * v1.w + w2 * v2.w + w3 * v3.w;
    }
    for (; j < cnt; j++) {
        int2 e0 = cs[j];
        float4 v0 = P4[(size_t)e0.x * 48 + 16 + lane];
        float w0 = __int_as_float(e0.y);
        acc.x += w0 * v0.x; acc.y += w0 * v0.y; acc.z += w0 * v0.z; acc.w += w0 * v0.w;
    }
    Q4[(size_t)node * 32 + lane] = acc;
}

// h1 = relu(P[:,0:64] + Q[:,0:64] + 2*Lhat(Q[:,64:128]) + b1): half-warp per node
__global__ void k_combine64(const float4* __restrict__ P4, const float4* __restrict__ Q4,
                            const float* __restrict__ b1, float4* __restrict__ H4) {
    int g = blockIdx.x * blockDim.x + threadIdx.x;
    int node = g >> 4;
    if (node >= NN) return;
    int lane = g & 15;
    int start = g_rowstart[node];
    int cnt = g_indeg[node];
    float4 p = P4[(size_t)node * 48 + lane];
    float4 q = Q4[(size_t)node * 32 + lane];
    float4 bb = *(const float4*)(b1 + lane * 4);
    float4 acc = make_float4(p.x + q.x + bb.x, p.y + q.y + bb.y,
                             p.z + q.z + bb.z, p.w + q.w + bb.w);
    const int2* cs = g_csr + start;
    int j = 0;
    for (; j + 4 <= cnt; j += 4) {
        int2 e0 = cs[j], e1 = cs[j + 1], e2 = cs[j + 2], e3 = cs[j + 3];
        float4 v0 = Q4[(size_t)e0.x * 32 + 16 + lane];
        float4 v1 = Q4[(size_t)e1.x * 32 + 16 + lane];
        float4 v2 = Q4[(size_t)e2.x * 32 + 16 + lane];
        float4 v3 = Q4[(size_t)e3.x * 32 + 16 + lane];
        float w0 = 2.f * __int_as_float(e0.y), w1 = 2.f * __int_as_float(e1.y);
        float w2 = 2.f * __int_as_float(e2.y), w3 = 2.f * __int_as_float(e3.y);
        acc.x += w0 * v0.x + w1 * v1.x + w2 * v2.x + w3 * v3.x;
        acc.y += w0 * v0.y + w1 * v1.y + w2 * v2.y + w3 * v3.y;
        acc.z += w0 * v0.z + w1 * v1.z + w2 * v2.z + w3 * v3.z;
        acc.w += w0 * v0.w + w1 * v1.w + w2 * v2.w + w3 * v3.w;
    }
    for (; j < cnt; j++) {
        int2 e0 = cs[j];
        float4 v0 = Q4[(size_t)e0.x * 32 + 16 + lane];
        float w0 = 2.f * __int_as_float(e0.y);
        acc.x += w0 * v0.x; acc.y += w0 * v0.y; acc.z += w0 * v0.z; acc.w += w0 * v0.w;
    }
    acc.x = fmaxf(acc.x, 0.f); acc.y = fmaxf(acc.y, 0.f);
    acc.z = fmaxf(acc.z, 0.f); acc.w = fmaxf(acc.w, 0.f);
    H4[(size_t)node * 16 + lane] = acc;
}

// generic D=64 gather: out = scale*Lhat(in) - (subsrc ? subsrc : 0)
__global__ void k_gather64(const float4* __restrict__ in, float4* __restrict__ out,
                           const float4* __restrict__ subsrc, float scale) {
    int g = blockIdx.x * blockDim.x + threadIdx.x;
    int node = g >> 4;
    if (node >= NN) return;
    int lane = g & 15;
    int start = g_rowstart[node];
    int cnt = g_indeg[node];
    float4 acc;
    if (subsrc) {
        float4 t = subsrc[(size_t)node * 16 + lane];
        acc = make_float4(-t.x, -t.y, -t.z, -t.w);
    } else {
        acc = make_float4(0.f, 0.f, 0.f, 0.f);
    }
    const int2* cs = g_csr + start;
    int j = 0;
    for (; j + 4 <= cnt; j += 4) {
        int2 e0 = cs[j], e1 = cs[j + 1], e2 = cs[j + 2], e3 = cs[j + 3];
        float4 v0 = in[(size_t)e0.x * 16 + lane];
        float4 v1 = in[(size_t)e1.x * 16 + lane];
        float4 v2 = in[(size_t)e2.x * 16 + lane];
        float4 v3 = in[(size_t)e3.x * 16 + lane];
        float w0 = __int_as_float(e0.y) * scale;
        float w1 = __int_as_float(e1.y) * scale;
        float w2 = __int_as_float(e2.y) * scale;
        float w3 = __int_as_float(e3.y) * scale;
        acc.x += w0 * v0.x + w1 * v1.x + w2 * v2.x + w3 * v3.x;
        acc.y += w0 * v0.y + w1 * v1.y + w2 * v2.y + w3 * v3.y;
        acc.z += w0 * v0.z + w1 * v1.z + w2 * v2.z + w3 * v3.z;
        acc.w += w0 * v0.w + w1 * v1.w + w2 * v2.w + w3 * v3.w;
    }
    for (; j < cnt; j++) {
        int2 e0 = cs[j];
        float4 v0 = in[(size_t)e0.x * 16 + lane];
        float w0 = __int_as_float(e0.y) * scale;
        acc.x += w0 * v0.x; acc.y += w0 * v0.y; acc.z += w0 * v0.z; acc.w += w0 * v0.w;
    }
    out[(size_t)node * 16 + lane] = acc;
}

// ---------------- GEMM: h2 = relu([h1|tb1|tb2] @ W2 + b2) ----------------
// BM=128, BN=64, BK=32, KTOT=192, same microtile as k_gemm_p.
__global__ void k_gemm3(const float4* __restrict__ A0, const float4* __restrict__ A1,
                        const float4* __restrict__ A2, const float* __restrict__ W,
                        const float* __restrict__ bias, float* __restrict__ C) {
    __shared__ float sA[32][132];
    __shared__ float sB[32][64];
    const int tid = threadIdx.x;
    const int m0 = blockIdx.x * 128;
    const int tx = tid & 15, ty = tid >> 4;
    const int lrow = tid >> 3, lcol4 = tid & 7;
    const int lrB = tid >> 4, lcB = (tid & 15) << 2;

    float acc[8][4];
#pragma unroll
    for (int i = 0; i < 8; i++)
#pragma unroll
        for (int j = 0; j < 4; j++) acc[i][j] = 0.f;

    for (int k0 = 0; k0 < 192; k0 += 32) {
        const float4* Asrc = (k0 < 64) ? A0 : (k0 < 128 ? A1 : A2);
        const int koff4 = (k0 & 63) >> 2;   // 0 or 8
#pragma unroll
        for (int r = 0; r < 4; r++) {
            int row = lrow + r * 32;
            int gm = m0 + row;
            float4 v = make_float4(0.f, 0.f, 0.f, 0.f);
            if (gm < NN) v = Asrc[(size_t)gm * 16 + koff4 + lcol4];
            sA[lcol4 * 4 + 0][row] = v.x;
            sA[lcol4 * 4 + 1][row] = v.y;
            sA[lcol4 * 4 + 2][row] = v.z;
            sA[lcol4 * 4 + 3][row] = v.w;
        }
#pragma unroll
        for (int rr = 0; rr < 2; rr++) {
            int row = lrB + rr * 16;
            float4 w4 = *(const float4*)(W + (size_t)(k0 + row) * 64 + lcB);
            sB[row][lcB + 0] = w4.x;
            sB[row][lcB + 1] = w4.y;
            sB[row][lcB + 2] = w4.z;
            sB[row][lcB + 3] = w4.w;
        }
        __syncthreads();
#pragma unroll
        for (int kk = 0; kk < 32; kk++) {
            float a[8], b[4];
#pragma unroll
            for (int i = 0; i < 8; i++) a[i] = sA[kk][ty * 8 + i];
#pragma unroll
            for (int j = 0; j < 4; j++) b[j] = sB[kk][tx * 4 + j];
#pragma unroll
            for (int i = 0; i < 8; i++)
#pragma unroll
                for (int j = 0; j < 4; j++) acc[i][j] = fmaf(a[i], b[j], acc[i][j]);
        }
        __syncthreads();
    }
    float4 bb = *(const float4*)(bias + tx * 4);
#pragma unroll
    for (int i = 0; i < 8; i++) {
        int gm = m0 + ty * 8 + i;
        if (gm < NN) {
            float4 o;
            o.x = fmaxf(acc[i][0] + bb.x, 0.f);
            o.y = fmaxf(acc[i][1] + bb.y, 0.f);
            o.z = fmaxf(acc[i][2] + bb.z, 0.f);
            o.w = fmaxf(acc[i][3] + bb.w, 0.f);
            *(float4*)(C + (size_t)gm * 64 + tx * 4) = o;
        }
    }
}

// ---------------- pooling + FC ----------------
__global__ void k_pool(const float* __restrict__ h) {
    int col = threadIdx.x & 63;
    int sub = threadIdx.x >> 6;
    int n0 = blockIdx.x * 128 + sub * 32;
    float acc = 0.f;
    int cur = -1;
    for (int k = 0; k < 32; k++) {
        int n = n0 + k;
        if (n >= NN) break;
        int gph = g_batch[n];
        if (gph != cur) {
            if (cur >= 0) atomicAdd(&g_gsum[cur * 64 + col], acc);
            cur = gph;
            acc = 0.f;
        }
        acc += h[(size_t)n * 64 + col];
    }
    if (cur >= 0) atomicAdd(&g_gsum[cur * 64 + col], acc);
}

__global__ void k_final(const float* __restrict__ Wfc, const float* __restrict__ bfc,
                        float* __restrict__ out) {
    int gph = threadIdx.x;
    if (gph < NG) {
        float c = fmaxf(g_gcnt[gph], 1.0f);
        float s = 0.f;
#pragma unroll
        for (int o = 0; o < 64; o++) s += g_gsum[gph * 64 + o] * Wfc[o];
        out[gph] = s / c + bfc[0];
    }
}

// ---------------- launch ----------------
extern "C" void kernel_launch(void* const* d_in, const int* in_sizes, int n_in,
                              void* d_out, int out_size) {
    const float *x = nullptr, *W1 = nullptr, *b1 = nullptr, *W2 = nullptr,
                *b2 = nullptr, *Wfc = nullptr, *bfc = nullptr;
    const void *ei = nullptr, *batch = nullptr;
    int idx64[3] = {-1, -1, -1};
    int n64 = 0, idxW2 = -1;
    for (int i = 0; i < n_in; i++) {
        int s = in_sizes[i];
        switch (s) {
            case 12800000: x = (const float*)d_in[i]; break;
            case 6400000:  ei = d_in[i]; break;
            case 100000:   batch = d_in[i]; break;
            case 24576:    W1 = (const float*)d_in[i]; break;
            case 12288:    W2 = (const float*)d_in[i]; idxW2 = i; break;
            case 1:        bfc = (const float*)d_in[i]; break;
            case 64:       if (n64 < 3) idx64[n64++] = i; break;
            default: break;
        }
    }
    if (n64 == 3) {
        if (idx64[0] < idxW2) {
            b1 = (const float*)d_in[idx64[0]];
            b2 = (const float*)d_in[idx64[1]];
            Wfc = (const float*)d_in[idx64[2]];
        } else {
            Wfc = (const float*)d_in[idx64[0]];
            b1 = (const float*)d_in[idx64[1]];
            b2 = (const float*)d_in[idx64[2]];
        }
    }
    float* out = (float*)d_out;

    float4 *P, *Q, *h1, *tb1, *tb2, *h2;
    cudaGetSymbolAddress((void**)&P, g_P);
    cudaGetSymbolAddress((void**)&Q, g_Q);
    cudaGetSymbolAddress((void**)&h1, g_h1);
    cudaGetSymbolAddress((void**)&tb1, g_tb1);
    cudaGetSymbolAddress((void**)&tb2, g_tb2);
    cudaGetSymbolAddress((void**)&h2, g_h2);

    const int TB = 256;

    // prep + CSR build
    k_detect<<<1, 256>>>((const int*)ei, (const int*)batch);
    k_zero_small<<<(NN + TB - 1) / TB, TB>>>();
    k_deg_prep<<<(NE / 2 + TB - 1) / TB, TB>>>(ei);
    k_batch_prep<<<(NN + TB - 1) / TB, TB>>>(batch);
    k_alloc<<<(NN + TB - 1) / TB, TB>>>();
    k_fill<<<(NE + TB - 1) / TB, TB>>>();
    k_wcat<<<(DIN * 192 + TB - 1) / TB, TB>>>(W1);

    // layer 1: P = x@Wcat; Q = Lhat(P[:,64:192]); h1 = relu(P0 + Q1 + 2*Lhat(Q2) + b1)
    {
        dim3 gp((NN + 127) / 128, 3);
        k_gemm_p<<<gp, TB>>>((const float4*)x, (float*)P);
        k_gather128q<<<(NN * 32 + TB - 1) / TB, TB>>>(P, Q);
        k_combine64<<<(NN * 16 + TB - 1) / TB, TB>>>(P, Q, b1, h1);
    }

    // layer 2: tb1 = Lhat(h1); tb2 = 2*Lhat(tb1) - h1; h2 = relu([h1|tb1|tb2]@W2 + b2)
    {
        int g64 = (NN * 16 + TB - 1) / TB;
        k_gather64<<<g64, TB>>>(h1, tb1, nullptr, 1.0f);
        k_gather64<<<g64, TB>>>(tb1, tb2, h1, 2.0f);
        k_gemm3<<<(NN + 127) / 128, TB>>>(h1, tb1, tb2, W2, b2, (float*)h2);
    }

    // mean pool per graph + FC
    k_pool<<<(NN + 127) / 128, TB>>>((const float*)h2);
    k_final<<<1, TB>>>(Wfc, bfc, out);
}

// round 7
// speedup vs baseline: 3.4644x; 1.2385x over previous
#include <cuda_runtime.h>
#include <cuda_fp16.h>
#include <cstddef>

#define NN 100000
#define NE 3200000
#define NG 256
#define DIN 128
#define DH 64

// ---------------- scratch (device globals; no allocation) ----------------
__device__ float  g_deg[NN];
__device__ float  g_dinv[NN];
__device__ int    g_src[NE];
__device__ int    g_dst[NE];
__device__ int    g_indeg[NN];
__device__ int    g_rowstart[NN];
__device__ int    g_fill[NN];
__device__ int    g_alloc;
__device__ int2   g_csr[NE];          // {src, bitcast(fp32 weight)}
__device__ int    g_batch[NN];
__device__ int    g_gstart[NG];
__device__ int    g_gend[NG];
__device__ int    g_flags[2];
__device__ float  g_wcat[DIN * 192];  // [W0-W2 | W1 | W2] for layer 1
// fp16 storage (uint2 = 4 halves, 8B aligned)
__device__ uint2  g_P[(size_t)NN * 48];   // x @ wcat, 192 halves/row
__device__ uint2  g_Q[(size_t)NN * 32];   // Lhat(P[:,64:192]), 128 halves/row
__device__ uint2  g_h1[(size_t)NN * 16];  // 64 halves/row
__device__ uint2  g_tb1[(size_t)NN * 16];
__device__ uint2  g_tb2[(size_t)NN * 16];
__device__ float4 g_h2[(size_t)NN * 16];  // fp32 (pool input)
__device__ float  g_gsum[NG * DH];

// ---------------- fp16 pack/unpack ----------------
__device__ __forceinline__ float4 ld_h4(const uint2* p) {
    uint2 u = *p;
    __half2 h0 = *reinterpret_cast<__half2*>(&u.x);
    __half2 h1 = *reinterpret_cast<__half2*>(&u.y);
    float2 f0 = __half22float2(h0), f1 = __half22float2(h1);
    return make_float4(f0.x, f0.y, f1.x, f1.y);
}
__device__ __forceinline__ uint2 st_h4(float4 v) {
    __half2 h0 = __floats2half2_rn(v.x, v.y);
    __half2 h1 = __floats2half2_rn(v.z, v.w);
    uint2 u;
    u.x = *reinterpret_cast<unsigned*>(&h0);
    u.y = *reinterpret_cast<unsigned*>(&h1);
    return u;
}

// ---------------- dtype probe ----------------
__global__ void k_detect(const int* __restrict__ ei_raw, const int* __restrict__ batch_raw) {
    __shared__ int s_ei, s_b;
    int t = threadIdx.x;
    if (t == 0) { s_ei = 0; s_b = 0; }
    __syncthreads();
    int acc_e = 0, acc_b = 0;
    for (int k = t; k < 4096; k += blockDim.x) acc_e |= ei_raw[2 * k + 1];
    for (int k = t; k < 4096; k += blockDim.x) acc_b |= batch_raw[2 * k + 1];
    atomicOr(&s_ei, acc_e);
    atomicOr(&s_b, acc_b);
    __syncthreads();
    if (t == 0) {
        g_flags[0] = (s_ei == 0) ? 1 : 0;
        g_flags[1] = (s_b == 0) ? 1 : 0;
    }
}

// ---------------- prep ----------------
__global__ void k_zero_small() {
    int i = blockIdx.x * blockDim.x + threadIdx.x;
    if (i < NN) { g_deg[i] = 0.f; g_indeg[i] = 0; g_fill[i] = 0; }
    if (i < NG * DH) g_gsum[i] = 0.f;
    if (i < NG) { g_gstart[i] = 0; g_gend[i] = 0; }
    if (i == 0) g_alloc = 0;
}

__global__ void k_deg_prep(const void* __restrict__ ei_raw) {
    int t = blockIdx.x * blockDim.x + threadIdx.x;
    int e = t * 2;
    if (e >= NE) return;
    int s0, s1, d0, d1;
    if (g_flags[0]) {
        longlong2 sp = ((const longlong2*)ei_raw)[t];
        longlong2 dp = ((const longlong2*)((const long long*)ei_raw + NE))[t];
        s0 = (int)sp.x; s1 = (int)sp.y;
        d0 = (int)dp.x; d1 = (int)dp.y;
    } else {
        int2 sp = ((const int2*)ei_raw)[t];
        int2 dp = ((const int2*)((const int*)ei_raw + NE))[t];
        s0 = sp.x; s1 = sp.y;
        d0 = dp.x; d1 = dp.y;
    }
    s0 = min(max(s0, 0), NN - 1); s1 = min(max(s1, 0), NN - 1);
    d0 = min(max(d0, 0), NN - 1); d1 = min(max(d1, 0), NN - 1);
    g_src[e] = s0; g_src[e + 1] = s1;
    g_dst[e] = d0; g_dst[e + 1] = d1;
    atomicAdd(&g_deg[s0], 1.0f);
    atomicAdd(&g_deg[s1], 1.0f);
    atomicAdd(&g_indeg[d0], 1);
    atomicAdd(&g_indeg[d1], 1);
}

__global__ void k_batch_prep(const void* __restrict__ batch_raw) {
    int i = blockIdx.x * blockDim.x + threadIdx.x;
    if (i >= NN) return;
    int b;
    if (g_flags[1]) b = (int)((const long long*)batch_raw)[i];
    else            b = ((const int*)batch_raw)[i];
    g_batch[i] = min(max(b, 0), NG - 1);
}

// batch is sorted -> counts from run boundaries; no atomics
__global__ void k_bounds() {
    int i = blockIdx.x * blockDim.x + threadIdx.x;
    if (i >= NN) return;
    int b = g_batch[i];
    if (i == 0 || g_batch[i - 1] != b) g_gstart[b] = i;
    if (i == NN - 1 || g_batch[i + 1] != b) g_gend[b] = i + 1;
}

// dinv + CSR row allocation (warp-scan, one atomicAdd per warp)
__global__ void k_alloc() {
    int i = blockIdx.x * blockDim.x + threadIdx.x;
    int lane = threadIdx.x & 31;
    if (i < NN) {
        float d = g_deg[i];
        g_dinv[i] = (d > 0.f) ? rsqrtf(d) : 0.f;
    }
    int v = (i < NN) ? g_indeg[i] : 0;
    int s = v;
#pragma unroll
    for (int o = 1; o < 32; o <<= 1) {
        int t = __shfl_up_sync(0xFFFFFFFF, s, o);
        if (lane >= o) s += t;
    }
    int total = __shfl_sync(0xFFFFFFFF, s, 31);
    int base = 0;
    if (lane == 31) base = atomicAdd(&g_alloc, total);
    base = __shfl_sync(0xFFFFFFFF, base, 31);
    if (i < NN) g_rowstart[i] = base + s - v;
}

__global__ void k_fill() {
    int e = blockIdx.x * blockDim.x + threadIdx.x;
    if (e >= NE) return;
    int s = g_src[e], d = g_dst[e];
    float w = -g_dinv[s] * g_dinv[d];
    int pos = atomicAdd(&g_fill[d], 1);
    int2 ent;
    ent.x = s;
    ent.y = __float_as_int(w);
    g_csr[g_rowstart[d] + pos] = ent;
}

// build Wcat = [W0-W2 | W1 | W2] (128 x 192)
__global__ void k_wcat(const float* __restrict__ W1) {
    int t = blockIdx.x * blockDim.x + threadIdx.x;
    if (t >= DIN * 192) return;
    int i = t / 192, o = t % 192;
    float v;
    if (o < 64)       v = W1[i * 64 + o] - W1[2 * 8192 + i * 64 + o];
    else if (o < 128) v = W1[8192 + i * 64 + (o - 64)];
    else              v = W1[2 * 8192 + i * 64 + (o - 128)];
    g_wcat[t] = v;
}

// ---------------- GEMM: P = x @ Wcat  (N x 128) @ (128 x 192), fp16 out ----------------
__global__ void k_gemm_p(const float4* __restrict__ A4) {
    __shared__ float sA[32][132];
    __shared__ float sB[32][64];
    const int tid = threadIdx.x;
    const int m0 = blockIdx.x * 128;
    const int n0 = blockIdx.y * 64;
    const int tx = tid & 15, ty = tid >> 4;
    const int lrow = tid >> 3, lcol4 = tid & 7;
    const int lrB = tid >> 4, lcB = (tid & 15) << 2;

    float acc[8][4];
#pragma unroll
    for (int i = 0; i < 8; i++)
#pragma unroll
        for (int j = 0; j < 4; j++) acc[i][j] = 0.f;

    for (int k0 = 0; k0 < 128; k0 += 32) {
#pragma unroll
        for (int r = 0; r < 4; r++) {
            int row = lrow + r * 32;
            int gm = m0 + row;
            float4 v = make_float4(0.f, 0.f, 0.f, 0.f);
            if (gm < NN) v = A4[(size_t)gm * 32 + (k0 >> 2) + lcol4];
            sA[lcol4 * 4 + 0][row] = v.x;
            sA[lcol4 * 4 + 1][row] = v.y;
            sA[lcol4 * 4 + 2][row] = v.z;
            sA[lcol4 * 4 + 3][row] = v.w;
        }
#pragma unroll
        for (int rr = 0; rr < 2; rr++) {
            int row = lrB + rr * 16;
            float4 w4 = *(const float4*)(g_wcat + (size_t)(k0 + row) * 192 + n0 + lcB);
            sB[row][lcB + 0] = w4.x;
            sB[row][lcB + 1] = w4.y;
            sB[row][lcB + 2] = w4.z;
            sB[row][lcB + 3] = w4.w;
        }
        __syncthreads();
#pragma unroll
        for (int kk = 0; kk < 32; kk++) {
            float a[8], b[4];
#pragma unroll
            for (int i = 0; i < 8; i++) a[i] = sA[kk][ty * 8 + i];
#pragma unroll
            for (int j = 0; j < 4; j++) b[j] = sB[kk][tx * 4 + j];
#pragma unroll
            for (int i = 0; i < 8; i++)
#pragma unroll
                for (int j = 0; j < 4; j++) acc[i][j] = fmaf(a[i], b[j], acc[i][j]);
        }
        __syncthreads();
    }
#pragma unroll
    for (int i = 0; i < 8; i++) {
        int gm = m0 + ty * 8 + i;
        if (gm < NN)
            g_P[(size_t)gm * 48 + (n0 >> 2) + tx] =
                st_h4(make_float4(acc[i][0], acc[i][1], acc[i][2], acc[i][3]));
    }
}

// ---------------- gathers (fp16 in, fp32 accumulate) ----------------
// Q = Lhat(P[:,64:192]): warp per node, lane owns 4 halves (uint2)
__global__ void k_gather128q() {
    int g = blockIdx.x * blockDim.x + threadIdx.x;
    int node = g >> 5;
    if (node >= NN) return;
    int lane = g & 31;
    int start = g_rowstart[node];
    int cnt = g_indeg[node];
    float4 acc = make_float4(0.f, 0.f, 0.f, 0.f);
    const int2* cs = g_csr + start;
    int j = 0;
    for (; j + 4 <= cnt; j += 4) {
        int2 e0 = cs[j], e1 = cs[j + 1], e2 = cs[j + 2], e3 = cs[j + 3];
        float4 v0 = ld_h4(g_P + (size_t)e0.x * 48 + 16 + lane);
        float4 v1 = ld_h4(g_P + (size_t)e1.x * 48 + 16 + lane);
        float4 v2 = ld_h4(g_P + (size_t)e2.x * 48 + 16 + lane);
        float4 v3 = ld_h4(g_P + (size_t)e3.x * 48 + 16 + lane);
        float w0 = __int_as_float(e0.y), w1 = __int_as_float(e1.y);
        float w2 = __int_as_float(e2.y), w3 = __int_as_float(e3.y);
        acc.x += w0 * v0.x + w1 * v1.x + w2 * v2.x + w3 * v3.x;
        acc.y += w0 * v0.y + w1 * v1.y + w2 * v2.y + w3 * v3.y;
        acc.z += w0 * v0.z + w1 * v1.z + w2 * v2.z + w3 * v3.z;
        acc.w += w0 * v0.w + w1 * v1.w + w2 * v2.w + w3 * v3.w;
    }
    for (; j < cnt; j++) {
        int2 e0 = cs[j];
        float4 v0 = ld_h4(g_P + (size_t)e0.x * 48 + 16 + lane);
        float w0 = __int_as_float(e0.y);
        acc.x += w0 * v0.x; acc.y += w0 * v0.y; acc.z += w0 * v0.z; acc.w += w0 * v0.w;
    }
    g_Q[(size_t)node * 32 + lane] = st_h4(acc);
}

// h1 = relu(P[:,0:64] + Q[:,0:64] + 2*Lhat(Q[:,64:128]) + b1): half-warp per node
__global__ void k_combine64(const float* __restrict__ b1) {
    int g = blockIdx.x * blockDim.x + threadIdx.x;
    int node = g >> 4;
    if (node >= NN) return;
    int lane = g & 15;
    int start = g_rowstart[node];
    int cnt = g_indeg[node];
    float4 p = ld_h4(g_P + (size_t)node * 48 + lane);
    float4 q = ld_h4(g_Q + (size_t)node * 32 + lane);
    float4 bb = *(const float4*)(b1 + lane * 4);
    float4 acc = make_float4(p.x + q.x + bb.x, p.y + q.y + bb.y,
                             p.z + q.z + bb.z, p.w + q.w + bb.w);
    const int2* cs = g_csr + start;
    int j = 0;
    for (; j + 4 <= cnt; j += 4) {
        int2 e0 = cs[j], e1 = cs[j + 1], e2 = cs[j + 2], e3 = cs[j + 3];
        float4 v0 = ld_h4(g_Q + (size_t)e0.x * 32 + 16 + lane);
        float4 v1 = ld_h4(g_Q + (size_t)e1.x * 32 + 16 + lane);
        float4 v2 = ld_h4(g_Q + (size_t)e2.x * 32 + 16 + lane);
        float4 v3 = ld_h4(g_Q + (size_t)e3.x * 32 + 16 + lane);
        float w0 = 2.f * __int_as_float(e0.y), w1 = 2.f * __int_as_float(e1.y);
        float w2 = 2.f * __int_as_float(e2.y), w3 = 2.f * __int_as_float(e3.y);
        acc.x += w0 * v0.x + w1 * v1.x + w2 * v2.x + w3 * v3.x;
        acc.y += w0 * v0.y + w1 * v1.y + w2 * v2.y + w3 * v3.y;
        acc.z += w0 * v0.z + w1 * v1.z + w2 * v2.z + w3 * v3.z;
        acc.w += w0 * v0.w + w1 * v1.w + w2 * v2.w + w3 * v3.w;
    }
    for (; j < cnt; j++) {
        int2 e0 = cs[j];
        float4 v0 = ld_h4(g_Q + (size_t)e0.x * 32 + 16 + lane);
        float w0 = 2.f * __int_as_float(e0.y);
        acc.x += w0 * v0.x; acc.y += w0 * v0.y; acc.z += w0 * v0.z; acc.w += w0 * v0.w;
    }
    acc.x = fmaxf(acc.x, 0.f); acc.y = fmaxf(acc.y, 0.f);
    acc.z = fmaxf(acc.z, 0.f); acc.w = fmaxf(acc.w, 0.f);
    g_h1[(size_t)node * 16 + lane] = st_h4(acc);
}

// generic D=64 gather: out = scale*Lhat(in) - (sub ? in-src : 0), fp16
__global__ void k_gather64(const uint2* __restrict__ in, uint2* __restrict__ out,
                           const uint2* __restrict__ subsrc, float scale) {
    int g = blockIdx.x * blockDim.x + threadIdx.x;
    int node = g >> 4;
    if (node >= NN) return;
    int lane = g & 15;
    int start = g_rowstart[node];
    int cnt = g_indeg[node];
    float4 acc;
    if (subsrc) {
        float4 t = ld_h4(subsrc + (size_t)node * 16 + lane);
        acc = make_float4(-t.x, -t.y, -t.z, -t.w);
    } else {
        acc = make_float4(0.f, 0.f, 0.f, 0.f);
    }
    const int2* cs = g_csr + start;
    int j = 0;
    for (; j + 4 <= cnt; j += 4) {
        int2 e0 = cs[j], e1 = cs[j + 1], e2 = cs[j + 2], e3 = cs[j + 3];
        float4 v0 = ld_h4(in + (size_t)e0.x * 16 + lane);
        float4 v1 = ld_h4(in + (size_t)e1.x * 16 + lane);
        float4 v2 = ld_h4(in + (size_t)e2.x * 16 + lane);
        float4 v3 = ld_h4(in + (size_t)e3.x * 16 + lane);
        float w0 = __int_as_float(e0.y) * scale;
        float w1 = __int_as_float(e1.y) * scale;
        float w2 = __int_as_float(e2.y) * scale;
        float w3 = __int_as_float(e3.y) * scale;
        acc.x += w0 * v0.x + w1 * v1.x + w2 * v2.x + w3 * v3.x;
        acc.y += w0 * v0.y + w1 * v1.y + w2 * v2.y + w3 * v3.y;
        acc.z += w0 * v0.z + w1 * v1.z + w2 * v2.z + w3 * v3.z;
        acc.w += w0 * v0.w + w1 * v1.w + w2 * v2.w + w3 * v3.w;
    }
    for (; j < cnt; j++) {
        int2 e0 = cs[j];
        float4 v0 = ld_h4(in + (size_t)e0.x * 16 + lane);
        float w0 = __int_as_float(e0.y) * scale;
        acc.x += w0 * v0.x; acc.y += w0 * v0.y; acc.z += w0 * v0.z; acc.w += w0 * v0.w;
    }
    out[(size_t)node * 16 + lane] = st_h4(acc);
}

// ---------------- GEMM: h2 = relu([h1|tb1|tb2] @ W2 + b2), fp16 A, fp32 out ----------------
__global__ void k_gemm3(const float* __restrict__ W, const float* __restrict__ bias) {
    __shared__ float sA[32][132];
    __shared__ float sB[32][64];
    const int tid = threadIdx.x;
    const int m0 = blockIdx.x * 128;
    const int tx = tid & 15, ty = tid >> 4;
    const int lrow = tid >> 3, lcol4 = tid & 7;
    const int lrB = tid >> 4, lcB = (tid & 15) << 2;

    float acc[8][4];
#pragma unroll
    for (int i = 0; i < 8; i++)
#pragma unroll
        for (int j = 0; j < 4; j++) acc[i][j] = 0.f;

    for (int k0 = 0; k0 < 192; k0 += 32) {
        const uint2* Asrc = (k0 < 64) ? g_h1 : (k0 < 128 ? g_tb1 : g_tb2);
        const int koff = (k0 & 63) >> 2;   // uint2 offset: 0 or 8
#pragma unroll
        for (int r = 0; r < 4; r++) {
            int row = lrow + r * 32;
            int gm = m0 + row;
            float4 v = make_float4(0.f, 0.f, 0.f, 0.f);
            if (gm < NN) v = ld_h4(Asrc + (size_t)gm * 16 + koff + lcol4);
            sA[lcol4 * 4 + 0][row] = v.x;
            sA[lcol4 * 4 + 1][row] = v.y;
            sA[lcol4 * 4 + 2][row] = v.z;
            sA[lcol4 * 4 + 3][row] = v.w;
        }
#pragma unroll
        for (int rr = 0; rr < 2; rr++) {
            int row = lrB + rr * 16;
            float4 w4 = *(const float4*)(W + (size_t)(k0 + row) * 64 + lcB);
            sB[row][lcB + 0] = w4.x;
            sB[row][lcB + 1] = w4.y;
            sB[row][lcB + 2] = w4.z;
            sB[row][lcB + 3] = w4.w;
        }
        __syncthreads();
#pragma unroll
        for (int kk = 0; kk < 32; kk++) {
            float a[8], b[4];
#pragma unroll
            for (int i = 0; i < 8; i++) a[i] = sA[kk][ty * 8 + i];
#pragma unroll
            for (int j = 0; j < 4; j++) b[j] = sB[kk][tx * 4 + j];
#pragma unroll
            for (int i = 0; i < 8; i++)
#pragma unroll
                for (int j = 0; j < 4; j++) acc[i][j] = fmaf(a[i], b[j], acc[i][j]);
        }
        __syncthreads();
    }
    float4 bb = *(const float4*)(bias + tx * 4);
#pragma unroll
    for (int i = 0; i < 8; i++) {
        int gm = m0 + ty * 8 + i;
        if (gm < NN) {
            float4 o;
            o.x = fmaxf(acc[i][0] + bb.x, 0.f);
            o.y = fmaxf(acc[i][1] + bb.y, 0.f);
            o.z = fmaxf(acc[i][2] + bb.z, 0.f);
            o.w = fmaxf(acc[i][3] + bb.w, 0.f);
            g_h2[(size_t)gm * 16 + tx] = o;
        }
    }
}

// ---------------- pooling + FC ----------------
__global__ void k_pool() {
    int col = threadIdx.x & 63;
    int sub = threadIdx.x >> 6;
    int n0 = blockIdx.x * 128 + sub * 32;
    const float* h = (const float*)g_h2;
    float acc = 0.f;
    int cur = -1;
    for (int k = 0; k < 32; k++) {
        int n = n0 + k;
        if (n >= NN) break;
        int gph = g_batch[n];
        if (gph != cur) {
            if (cur >= 0) atomicAdd(&g_gsum[cur * 64 + col], acc);
            cur = gph;
            acc = 0.f;
        }
        acc += h[(size_t)n * 64 + col];
    }
    if (cur >= 0) atomicAdd(&g_gsum[cur * 64 + col], acc);
}

__global__ void k_final(const float* __restrict__ Wfc, const float* __restrict__ bfc,
                        float* __restrict__ out) {
    int gph = threadIdx.x;
    if (gph < NG) {
        float c = fmaxf((float)(g_gend[gph] - g_gstart[gph]), 1.0f);
        float s = 0.f;
#pragma unroll
        for (int o = 0; o < 64; o++) s += g_gsum[gph * 64 + o] * Wfc[o];
        out[gph] = s / c + bfc[0];
    }
}

// ---------------- launch ----------------
extern "C" void kernel_launch(void* const* d_in, const int* in_sizes, int n_in,
                              void* d_out, int out_size) {
    const float *x = nullptr, *W1 = nullptr, *b1 = nullptr, *W2 = nullptr,
                *b2 = nullptr, *Wfc = nullptr, *bfc = nullptr;
    const void *ei = nullptr, *batch = nullptr;
    int idx64[3] = {-1, -1, -1};
    int n64 = 0, idxW2 = -1;
    for (int i = 0; i < n_in; i++) {
        int s = in_sizes[i];
        switch (s) {
            case 12800000: x = (const float*)d_in[i]; break;
            case 6400000:  ei = d_in[i]; break;
            case 100000:   batch = d_in[i]; break;
            case 24576:    W1 = (const float*)d_in[i]; break;
            case 12288:    W2 = (const float*)d_in[i]; idxW2 = i; break;
            case 1:        bfc = (const float*)d_in[i]; break;
            case 64:       if (n64 < 3) idx64[n64++] = i; break;
            default: break;
        }
    }
    if (n64 == 3) {
        if (idx64[0] < idxW2) {
            b1 = (const float*)d_in[idx64[0]];
            b2 = (const float*)d_in[idx64[1]];
            Wfc = (const float*)d_in[idx64[2]];
        } else {
            Wfc = (const float*)d_in[idx64[0]];
            b1 = (const float*)d_in[idx64[1]];
            b2 = (const float*)d_in[idx64[2]];
        }
    }
    float* out = (float*)d_out;

    uint2 *h1, *tb1, *tb2;
    cudaGetSymbolAddress((void**)&h1, g_h1);
    cudaGetSymbolAddress((void**)&tb1, g_tb1);
    cudaGetSymbolAddress((void**)&tb2, g_tb2);

    const int TB = 256;

    // prep + CSR build
    k_detect<<<1, 256>>>((const int*)ei, (const int*)batch);
    k_zero_small<<<(NN + TB - 1) / TB, TB>>>();
    k_deg_prep<<<(NE / 2 + TB - 1) / TB, TB>>>(ei);
    k_batch_prep<<<(NN + TB - 1) / TB, TB>>>(batch);
    k_bounds<<<(NN + TB - 1) / TB, TB>>>();
    k_alloc<<<(NN + TB - 1) / TB, TB>>>();
    k_fill<<<(NE + TB - 1) / TB, TB>>>();
    k_wcat<<<(DIN * 192 + TB - 1) / TB, TB>>>(W1);

    // layer 1: P = x@Wcat; Q = Lhat(P[:,64:192]); h1 = relu(P0 + Q1 + 2*Lhat(Q2) + b1)
    {
        dim3 gp((NN + 127) / 128, 3);
        k_gemm_p<<<gp, TB>>>((const float4*)x);
        k_gather128q<<<(NN * 32 + TB - 1) / TB, TB>>>();
        k_combine64<<<(NN * 16 + TB - 1) / TB, TB>>>(b1);
    }

    // layer 2: tb1 = Lhat(h1); tb2 = 2*Lhat(tb1) - h1; h2 = relu([h1|tb1|tb2]@W2 + b2)
    {
        int g64 = (NN * 16 + TB - 1) / TB;
        k_gather64<<<g64, TB>>>(h1, tb1, nullptr, 1.0f);
        k_gather64<<<g64, TB>>>(tb1, tb2, h1, 2.0f);
        k_gemm3<<<(NN + 127) / 128, TB>>>(W2, b2);
    }

    // mean pool per graph + FC
    k_pool<<<(NN + 127) / 128, TB>>>();
    k_final<<<1, TB>>>(Wfc, bfc, out);
}

// round 8
// speedup vs baseline: 3.9100x; 1.1286x over previous
#include <cuda_runtime.h>
#include <cuda_fp16.h>
#include <mma.h>
#include <cstddef>

using namespace nvcuda;

#define NN 100000
#define NE 3200000
#define NG 256
#define DIN 128
#define DH 64

// ---------------- scratch (device globals; no allocation) ----------------
__device__ float  g_deg[NN];
__device__ float  g_dinv[NN];
__device__ int    g_src[NE];
__device__ int    g_dst[NE];
__device__ int    g_indeg[NN];
__device__ int    g_rowstart[NN];
__device__ int    g_fill[NN];
__device__ int    g_alloc;
__device__ int2   g_csr[NE];          // {src, bitcast(fp32 weight)}
__device__ int    g_batch[NN];
__device__ int    g_gstart[NG];
__device__ int    g_gend[NG];
__device__ int    g_flags[2];
__device__ float  g_wcat[DIN * 192];  // [W0-W2 | W1 | W2] for layer 1
// fp16 storage (uint2 = 4 halves, 8B aligned)
__device__ uint2  g_P[(size_t)NN * 48];   // x @ wcat, 192 halves/row
__device__ uint2  g_Q[(size_t)NN * 32];   // Lhat(P[:,64:192]), 128 halves/row
__device__ uint2  g_h1[(size_t)NN * 16];  // 64 halves/row
__device__ uint2  g_tb1[(size_t)NN * 16];
__device__ uint2  g_tb2[(size_t)NN * 16];
__device__ float4 g_h2[(size_t)NN * 16];  // fp32 (pool input)
__device__ float  g_gsum[NG * DH];

// ---------------- fp16 pack/unpack ----------------
__device__ __forceinline__ float4 ld_h4(const uint2* p) {
    uint2 u = *p;
    __half2 h0 = *reinterpret_cast<__half2*>(&u.x);
    __half2 h1 = *reinterpret_cast<__half2*>(&u.y);
    float2 f0 = __half22float2(h0), f1 = __half22float2(h1);
    return make_float4(f0.x, f0.y, f1.x, f1.y);
}
__device__ __forceinline__ uint2 st_h4(float4 v) {
    __half2 h0 = __floats2half2_rn(v.x, v.y);
    __half2 h1 = __floats2half2_rn(v.z, v.w);
    uint2 u;
    u.x = *reinterpret_cast<unsigned*>(&h0);
    u.y = *reinterpret_cast<unsigned*>(&h1);
    return u;
}

// ---------------- dtype probe ----------------
__global__ void k_detect(const int* __restrict__ ei_raw, const int* __restrict__ batch_raw) {
    __shared__ int s_ei, s_b;
    int t = threadIdx.x;
    if (t == 0) { s_ei = 0; s_b = 0; }
    __syncthreads();
    int acc_e = 0, acc_b = 0;
    for (int k = t; k < 4096; k += blockDim.x) acc_e |= ei_raw[2 * k + 1];
    for (int k = t; k < 4096; k += blockDim.x) acc_b |= batch_raw[2 * k + 1];
    atomicOr(&s_ei, acc_e);
    atomicOr(&s_b, acc_b);
    __syncthreads();
    if (t == 0) {
        g_flags[0] = (s_ei == 0) ? 1 : 0;
        g_flags[1] = (s_b == 0) ? 1 : 0;
    }
}

// ---------------- prep ----------------
__global__ void k_zero_small() {
    int i = blockIdx.x * blockDim.x + threadIdx.x;
    if (i < NN) { g_deg[i] = 0.f; g_indeg[i] = 0; g_fill[i] = 0; }
    if (i < NG * DH) g_gsum[i] = 0.f;
    if (i < NG) { g_gstart[i] = 0; g_gend[i] = 0; }
    if (i == 0) g_alloc = 0;
}

__global__ void k_deg_prep(const void* __restrict__ ei_raw) {
    int t = blockIdx.x * blockDim.x + threadIdx.x;
    int e = t * 2;
    if (e >= NE) return;
    int s0, s1, d0, d1;
    if (g_flags[0]) {
        longlong2 sp = ((const longlong2*)ei_raw)[t];
        longlong2 dp = ((const longlong2*)((const long long*)ei_raw + NE))[t];
        s0 = (int)sp.x; s1 = (int)sp.y;
        d0 = (int)dp.x; d1 = (int)dp.y;
    } else {
        int2 sp = ((const int2*)ei_raw)[t];
        int2 dp = ((const int2*)((const int*)ei_raw + NE))[t];
        s0 = sp.x; s1 = sp.y;
        d0 = dp.x; d1 = dp.y;
    }
    s0 = min(max(s0, 0), NN - 1); s1 = min(max(s1, 0), NN - 1);
    d0 = min(max(d0, 0), NN - 1); d1 = min(max(d1, 0), NN - 1);
    g_src[e] = s0; g_src[e + 1] = s1;
    g_dst[e] = d0; g_dst[e + 1] = d1;
    atomicAdd(&g_deg[s0], 1.0f);
    atomicAdd(&g_deg[s1], 1.0f);
    atomicAdd(&g_indeg[d0], 1);
    atomicAdd(&g_indeg[d1], 1);
}

__global__ void k_batch_prep(const void* __restrict__ batch_raw) {
    int i = blockIdx.x * blockDim.x + threadIdx.x;
    if (i >= NN) return;
    int b;
    if (g_flags[1]) b = (int)((const long long*)batch_raw)[i];
    else            b = ((const int*)batch_raw)[i];
    g_batch[i] = min(max(b, 0), NG - 1);
}

// batch is sorted -> counts from run boundaries; no atomics
__global__ void k_bounds() {
    int i = blockIdx.x * blockDim.x + threadIdx.x;
    if (i >= NN) return;
    int b = g_batch[i];
    if (i == 0 || g_batch[i - 1] != b) g_gstart[b] = i;
    if (i == NN - 1 || g_batch[i + 1] != b) g_gend[b] = i + 1;
}

// dinv + CSR row allocation (warp-scan, one atomicAdd per warp)
__global__ void k_alloc() {
    int i = blockIdx.x * blockDim.x + threadIdx.x;
    int lane = threadIdx.x & 31;
    if (i < NN) {
        float d = g_deg[i];
        g_dinv[i] = (d > 0.f) ? rsqrtf(d) : 0.f;
    }
    int v = (i < NN) ? g_indeg[i] : 0;
    int s = v;
#pragma unroll
    for (int o = 1; o < 32; o <<= 1) {
        int t = __shfl_up_sync(0xFFFFFFFF, s, o);
        if (lane >= o) s += t;
    }
    int total = __shfl_sync(0xFFFFFFFF, s, 31);
    int base = 0;
    if (lane == 31) base = atomicAdd(&g_alloc, total);
    base = __shfl_sync(0xFFFFFFFF, base, 31);
    if (i < NN) g_rowstart[i] = base + s - v;
}

__global__ void k_fill() {
    int e = blockIdx.x * blockDim.x + threadIdx.x;
    if (e >= NE) return;
    int s = g_src[e], d = g_dst[e];
    float w = -g_dinv[s] * g_dinv[d];
    int pos = atomicAdd(&g_fill[d], 1);
    int2 ent;
    ent.x = s;
    ent.y = __float_as_int(w);
    g_csr[g_rowstart[d] + pos] = ent;
}

// build Wcat = [W0-W2 | W1 | W2] (128 x 192)
__global__ void k_wcat(const float* __restrict__ W1) {
    int t = blockIdx.x * blockDim.x + threadIdx.x;
    if (t >= DIN * 192) return;
    int i = t / 192, o = t % 192;
    float v;
    if (o < 64)       v = W1[i * 64 + o] - W1[2 * 8192 + i * 64 + o];
    else if (o < 128) v = W1[8192 + i * 64 + (o - 64)];
    else              v = W1[2 * 8192 + i * 64 + (o - 128)];
    g_wcat[t] = v;
}

// ---------------- tensor-core GEMM 1: P = x @ Wcat (fp16 in, fp32 acc, fp16 out) ----------------
// BM=128, BN=64, BK=32; 256 threads = 8 warps (4 along M x 2 along N), 2x2 frags each.
__global__ void k_gemm_p(const float4* __restrict__ A4) {
    __shared__ __align__(32) __half sA[128 * 40];   // ld=40
    __shared__ __align__(32) __half sB[32 * 72];    // ld=72
    __shared__ __align__(32) float  sC[128 * 64];   // staging
    const int tid = threadIdx.x;
    const int m0 = blockIdx.x * 128;
    const int n0 = blockIdx.y * 64;
    const int wid = tid >> 5;
    const int wm = wid & 3, wn = wid >> 2;

    wmma::fragment<wmma::accumulator, 16, 16, 16, float> c[2][2];
#pragma unroll
    for (int i = 0; i < 2; i++)
#pragma unroll
        for (int j = 0; j < 2; j++) wmma::fill_fragment(c[i][j], 0.f);

    const int arow = tid >> 1, aseg = tid & 1;       // A fill: 128 rows x 2 segs of 16
    const int brow = tid >> 3, bc8 = (tid & 7) * 8;  // B fill: 32 rows x 8 cols of 8

    for (int k0 = 0; k0 < 128; k0 += 32) {
        __syncthreads();
        {
            int gm = m0 + arow;
            uint2* dst = reinterpret_cast<uint2*>(sA) + arow * 10 + aseg * 4;
            if (gm < NN) {
                const float4* src = A4 + (size_t)gm * 32 + (k0 >> 2) + aseg * 4;
#pragma unroll
                for (int q = 0; q < 4; q++) dst[q] = st_h4(src[q]);
            } else {
                uint2 z = make_uint2(0u, 0u);
#pragma unroll
                for (int q = 0; q < 4; q++) dst[q] = z;
            }
        }
        {
            const float4* src = (const float4*)(g_wcat + (size_t)(k0 + brow) * 192 + n0 + bc8);
            uint2* dst = reinterpret_cast<uint2*>(sB) + brow * 18 + (tid & 7) * 2;
            dst[0] = st_h4(src[0]);
            dst[1] = st_h4(src[1]);
        }
        __syncthreads();
#pragma unroll
        for (int kk = 0; kk < 32; kk += 16) {
            wmma::fragment<wmma::matrix_a, 16, 16, 16, __half, wmma::row_major> a[2];
            wmma::fragment<wmma::matrix_b, 16, 16, 16, __half, wmma::row_major> b[2];
#pragma unroll
            for (int i = 0; i < 2; i++)
                wmma::load_matrix_sync(a[i], sA + (wm * 32 + i * 16) * 40 + kk, 40);
#pragma unroll
            for (int j = 0; j < 2; j++)
                wmma::load_matrix_sync(b[j], sB + kk * 72 + wn * 32 + j * 16, 72);
#pragma unroll
            for (int i = 0; i < 2; i++)
#pragma unroll
                for (int j = 0; j < 2; j++) wmma::mma_sync(c[i][j], a[i], b[j], c[i][j]);
        }
    }
#pragma unroll
    for (int i = 0; i < 2; i++)
#pragma unroll
        for (int j = 0; j < 2; j++)
            wmma::store_matrix_sync(sC + (wm * 32 + i * 16) * 64 + wn * 32 + j * 16,
                                    c[i][j], 64, wmma::mem_row_major);
    __syncthreads();
    {
        int row = tid >> 1, seg = tid & 1;
        int gm = m0 + row;
        if (gm < NN) {
            const float* src = sC + row * 64 + seg * 32;
            uint2* dst = g_P + (size_t)gm * 48 + (n0 >> 2) + seg * 8;
#pragma unroll
            for (int q = 0; q < 8; q++)
                dst[q] = st_h4(make_float4(src[q * 4], src[q * 4 + 1], src[q * 4 + 2], src[q * 4 + 3]));
        }
    }
}

// ---------------- gathers (fp16 in, fp32 accumulate) ----------------
__global__ void k_gather128q() {
    int g = blockIdx.x * blockDim.x + threadIdx.x;
    int node = g >> 5;
    if (node >= NN) return;
    int lane = g & 31;
    int start = g_rowstart[node];
    int cnt = g_indeg[node];
    float4 acc = make_float4(0.f, 0.f, 0.f, 0.f);
    const int2* cs = g_csr + start;
    int j = 0;
    for (; j + 4 <= cnt; j += 4) {
        int2 e0 = cs[j], e1 = cs[j + 1], e2 = cs[j + 2], e3 = cs[j + 3];
        float4 v0 = ld_h4(g_P + (size_t)e0.x * 48 + 16 + lane);
        float4 v1 = ld_h4(g_P + (size_t)e1.x * 48 + 16 + lane);
        float4 v2 = ld_h4(g_P + (size_t)e2.x * 48 + 16 + lane);
        float4 v3 = ld_h4(g_P + (size_t)e3.x * 48 + 16 + lane);
        float w0 = __int_as_float(e0.y), w1 = __int_as_float(e1.y);
        float w2 = __int_as_float(e2.y), w3 = __int_as_float(e3.y);
        acc.x += w0 * v0.x + w1 * v1.x + w2 * v2.x + w3 * v3.x;
        acc.y += w0 * v0.y + w1 * v1.y + w2 * v2.y + w3 * v3.y;
        acc.z += w0 * v0.z + w1 * v1.z + w2 * v2.z + w3 * v3.z;
        acc.w += w0 * v0.w + w1 * v1.w + w2 * v2.w + w3 * v3.w;
    }
    for (; j < cnt; j++) {
        int2 e0 = cs[j];
        float4 v0 = ld_h4(g_P + (size_t)e0.x * 48 + 16 + lane);
        float w0 = __int_as_float(e0.y);
        acc.x += w0 * v0.x; acc.y += w0 * v0.y; acc.z += w0 * v0.z; acc.w += w0 * v0.w;
    }
    g_Q[(size_t)node * 32 + lane] = st_h4(acc);
}

__global__ void k_combine64(const float* __restrict__ b1) {
    int g = blockIdx.x * blockDim.x + threadIdx.x;
    int node = g >> 4;
    if (node >= NN) return;
    int lane = g & 15;
    int start = g_rowstart[node];
    int cnt = g_indeg[node];
    float4 p = ld_h4(g_P + (size_t)node * 48 + lane);
    float4 q = ld_h4(g_Q + (size_t)node * 32 + lane);
    float4 bb = *(const float4*)(b1 + lane * 4);
    float4 acc = make_float4(p.x + q.x + bb.x, p.y + q.y + bb.y,
                             p.z + q.z + bb.z, p.w + q.w + bb.w);
    const int2* cs = g_csr + start;
    int j = 0;
    for (; j + 4 <= cnt; j += 4) {
        int2 e0 = cs[j], e1 = cs[j + 1], e2 = cs[j + 2], e3 = cs[j + 3];
        float4 v0 = ld_h4(g_Q + (size_t)e0.x * 32 + 16 + lane);
        float4 v1 = ld_h4(g_Q + (size_t)e1.x * 32 + 16 + lane);
        float4 v2 = ld_h4(g_Q + (size_t)e2.x * 32 + 16 + lane);
        float4 v3 = ld_h4(g_Q + (size_t)e3.x * 32 + 16 + lane);
        float w0 = 2.f * __int_as_float(e0.y), w1 = 2.f * __int_as_float(e1.y);
        float w2 = 2.f * __int_as_float(e2.y), w3 = 2.f * __int_as_float(e3.y);
        acc.x += w0 * v0.x + w1 * v1.x + w2 * v2.x + w3 * v3.x;
        acc.y += w0 * v0.y + w1 * v1.y + w2 * v2.y + w3 * v3.y;
        acc.z += w0 * v0.z + w1 * v1.z + w2 * v2.z + w3 * v3.z;
        acc.w += w0 * v0.w + w1 * v1.w + w2 * v2.w + w3 * v3.w;
    }
    for (; j < cnt; j++) {
        int2 e0 = cs[j];
        float4 v0 = ld_h4(g_Q + (size_t)e0.x * 32 + 16 + lane);
        float w0 = 2.f * __int_as_float(e0.y);
        acc.x += w0 * v0.x; acc.y += w0 * v0.y; acc.z += w0 * v0.z; acc.w += w0 * v0.w;
    }
    acc.x = fmaxf(acc.x, 0.f); acc.y = fmaxf(acc.y, 0.f);
    acc.z = fmaxf(acc.z, 0.f); acc.w = fmaxf(acc.w, 0.f);
    g_h1[(size_t)node * 16 + lane] = st_h4(acc);
}

__global__ void k_gather64(const uint2* __restrict__ in, uint2* __restrict__ out,
                           const uint2* __restrict__ subsrc, float scale) {
    int g = blockIdx.x * blockDim.x + threadIdx.x;
    int node = g >> 4;
    if (node >= NN) return;
    int lane = g & 15;
    int start = g_rowstart[node];
    int cnt = g_indeg[node];
    float4 acc;
    if (subsrc) {
        float4 t = ld_h4(subsrc + (size_t)node * 16 + lane);
        acc = make_float4(-t.x, -t.y, -t.z, -t.w);
    } else {
        acc = make_float4(0.f, 0.f, 0.f, 0.f);
    }
    const int2* cs = g_csr + start;
    int j = 0;
    for (; j + 4 <= cnt; j += 4) {
        int2 e0 = cs[j], e1 = cs[j + 1], e2 = cs[j + 2], e3 = cs[j + 3];
        float4 v0 = ld_h4(in + (size_t)e0.x * 16 + lane);
        float4 v1 = ld_h4(in + (size_t)e1.x * 16 + lane);
        float4 v2 = ld_h4(in + (size_t)e2.x * 16 + lane);
        float4 v3 = ld_h4(in + (size_t)e3.x * 16 + lane);
        float w0 = __int_as_float(e0.y) * scale;
        float w1 = __int_as_float(e1.y) * scale;
        float w2 = __int_as_float(e2.y) * scale;
        float w3 = __int_as_float(e3.y) * scale;
        acc.x += w0 * v0.x + w1 * v1.x + w2 * v2.x + w3 * v3.x;
        acc.y += w0 * v0.y + w1 * v1.y + w2 * v2.y + w3 * v3.y;
        acc.z += w0 * v0.z + w1 * v1.z + w2 * v2.z + w3 * v3.z;
        acc.w += w0 * v0.w + w1 * v1.w + w2 * v2.w + w3 * v3.w;
    }
    for (; j < cnt; j++) {
        int2 e0 = cs[j];
        float4 v0 = ld_h4(in + (size_t)e0.x * 16 + lane);
        float w0 = __int_as_float(e0.y) * scale;
        acc.x += w0 * v0.x; acc.y += w0 * v0.y; acc.z += w0 * v0.z; acc.w += w0 * v0.w;
    }
    out[(size_t)node * 16 + lane] = st_h4(acc);
}

// ---------------- tensor-core GEMM 2: h2 = relu([h1|tb1|tb2] @ W2 + b2) ----------------
__global__ void k_gemm3(const float* __restrict__ W, const float* __restrict__ bias) {
    __shared__ __align__(32) __half sA[128 * 40];
    __shared__ __align__(32) __half sB[32 * 72];
    __shared__ __align__(32) float  sC[128 * 64];
    const int tid = threadIdx.x;
    const int m0 = blockIdx.x * 128;
    const int wid = tid >> 5;
    const int wm = wid & 3, wn = wid >> 2;

    wmma::fragment<wmma::accumulator, 16, 16, 16, float> c[2][2];
#pragma unroll
    for (int i = 0; i < 2; i++)
#pragma unroll
        for (int j = 0; j < 2; j++) wmma::fill_fragment(c[i][j], 0.f);

    const int arow = tid >> 1, aseg = tid & 1;
    const int brow = tid >> 3, bc8 = (tid & 7) * 8;

    for (int k0 = 0; k0 < 192; k0 += 32) {
        const uint2* Asrc = (k0 < 64) ? g_h1 : (k0 < 128 ? g_tb1 : g_tb2);
        const int koff = (k0 & 63) >> 2;   // uint2 offset within row: 0 or 8
        __syncthreads();
        {
            int gm = m0 + arow;
            uint2* dst = reinterpret_cast<uint2*>(sA) + arow * 10 + aseg * 4;
            if (gm < NN) {
                const uint2* src = Asrc + (size_t)gm * 16 + koff + aseg * 4;
#pragma unroll
                for (int q = 0; q < 4; q++) dst[q] = src[q];
            } else {
                uint2 z = make_uint2(0u, 0u);
#pragma unroll
                for (int q = 0; q < 4; q++) dst[q] = z;
            }
        }
        {
            const float4* src = (const float4*)(W + (size_t)(k0 + brow) * 64 + bc8);
            uint2* dst = reinterpret_cast<uint2*>(sB) + brow * 18 + (tid & 7) * 2;
            dst[0] = st_h4(src[0]);
            dst[1] = st_h4(src[1]);
        }
        __syncthreads();
#pragma unroll
        for (int kk = 0; kk < 32; kk += 16) {
            wmma::fragment<wmma::matrix_a, 16, 16, 16, __half, wmma::row_major> a[2];
            wmma::fragment<wmma::matrix_b, 16, 16, 16, __half, wmma::row_major> b[2];
#pragma unroll
            for (int i = 0; i < 2; i++)
                wmma::load_matrix_sync(a[i], sA + (wm * 32 + i * 16) * 40 + kk, 40);
#pragma unroll
            for (int j = 0; j < 2; j++)
                wmma::load_matrix_sync(b[j], sB + kk * 72 + wn * 32 + j * 16, 72);
#pragma unroll
            for (int i = 0; i < 2; i++)
#pragma unroll
                for (int j = 0; j < 2; j++) wmma::mma_sync(c[i][j], a[i], b[j], c[i][j]);
        }
    }
#pragma unroll
    for (int i = 0; i < 2; i++)
#pragma unroll
        for (int j = 0; j < 2; j++)
            wmma::store_matrix_sync(sC + (wm * 32 + i * 16) * 64 + wn * 32 + j * 16,
                                    c[i][j], 64, wmma::mem_row_major);
    __syncthreads();
    {
        int row = tid >> 1, seg = tid & 1;
        int gm = m0 + row;
        if (gm < NN) {
            const float* src = sC + row * 64 + seg * 32;
#pragma unroll
            for (int q = 0; q < 8; q++) {
                float4 bb = *(const float4*)(bias + seg * 32 + q * 4);
                float4 o;
                o.x = fmaxf(src[q * 4 + 0] + bb.x, 0.f);
                o.y = fmaxf(src[q * 4 + 1] + bb.y, 0.f);
                o.z = fmaxf(src[q * 4 + 2] + bb.z, 0.f);
                o.w = fmaxf(src[q * 4 + 3] + bb.w, 0.f);
                g_h2[(size_t)gm * 16 + seg * 8 + q] = o;
            }
        }
    }
}

// ---------------- pooling + FC ----------------
__global__ void k_pool() {
    int col = threadIdx.x & 63;
    int sub = threadIdx.x >> 6;
    int n0 = blockIdx.x * 128 + sub * 32;
    const float* h = (const float*)g_h2;
    float acc = 0.f;
    int cur = -1;
    for (int k = 0; k < 32; k++) {
        int n = n0 + k;
        if (n >= NN) break;
        int gph = g_batch[n];
        if (gph != cur) {
            if (cur >= 0) atomicAdd(&g_gsum[cur * 64 + col], acc);
            cur = gph;
            acc = 0.f;
        }
        acc += h[(size_t)n * 64 + col];
    }
    if (cur >= 0) atomicAdd(&g_gsum[cur * 64 + col], acc);
}

__global__ void k_final(const float* __restrict__ Wfc, const float* __restrict__ bfc,
                        float* __restrict__ out) {
    int gph = threadIdx.x;
    if (gph < NG) {
        float c = fmaxf((float)(g_gend[gph] - g_gstart[gph]), 1.0f);
        float s = 0.f;
#pragma unroll
        for (int o = 0; o < 64; o++) s += g_gsum[gph * 64 + o] * Wfc[o];
        out[gph] = s / c + bfc[0];
    }
}

// ---------------- launch ----------------
extern "C" void kernel_launch(void* const* d_in, const int* in_sizes, int n_in,
                              void* d_out, int out_size) {
    const float *x = nullptr, *W1 = nullptr, *b1 = nullptr, *W2 = nullptr,
                *b2 = nullptr, *Wfc = nullptr, *bfc = nullptr;
    const void *ei = nullptr, *batch = nullptr;
    int idx64[3] = {-1, -1, -1};
    int n64 = 0, idxW2 = -1;
    for (int i = 0; i < n_in; i++) {
        int s = in_sizes[i];
        switch (s) {
            case 12800000: x = (const float*)d_in[i]; break;
            case 6400000:  ei = d_in[i]; break;
            case 100000:   batch = d_in[i]; break;
            case 24576:    W1 = (const float*)d_in[i]; break;
            case 12288:    W2 = (const float*)d_in[i]; idxW2 = i; break;
            case 1:        bfc = (const float*)d_in[i]; break;
            case 64:       if (n64 < 3) idx64[n64++] = i; break;
            default: break;
        }
    }
    if (n64 == 3) {
        if (idx64[0] < idxW2) {
            b1 = (const float*)d_in[idx64[0]];
            b2 = (const float*)d_in[idx64[1]];
            Wfc = (const float*)d_in[idx64[2]];
        } else {
            Wfc = (const float*)d_in[idx64[0]];
            b1 = (const float*)d_in[idx64[1]];
            b2 = (const float*)d_in[idx64[2]];
        }
    }
    float* out = (float*)d_out;

    uint2 *h1, *tb1, *tb2;
    cudaGetSymbolAddress((void**)&h1, g_h1);
    cudaGetSymbolAddress((void**)&tb1, g_tb1);
    cudaGetSymbolAddress((void**)&tb2, g_tb2);

    const int TB = 256;

    // prep + CSR build
    k_detect<<<1, 256>>>((const int*)ei, (const int*)batch);
    k_zero_small<<<(NN + TB - 1) / TB, TB>>>();
    k_deg_prep<<<(NE / 2 + TB - 1) / TB, TB>>>(ei);
    k_batch_prep<<<(NN + TB - 1) / TB, TB>>>(batch);
    k_bounds<<<(NN + TB - 1) / TB, TB>>>();
    k_alloc<<<(NN + TB - 1) / TB, TB>>>();
    k_fill<<<(NE + TB - 1) / TB, TB>>>();
    k_wcat<<<(DIN * 192 + TB - 1) / TB, TB>>>(W1);

    // layer 1: P = x@Wcat; Q = Lhat(P[:,64:192]); h1 = relu(P0 + Q1 + 2*Lhat(Q2) + b1)
    {
        dim3 gp((NN + 127) / 128, 3);
        k_gemm_p<<<gp, TB>>>((const float4*)x);
        k_gather128q<<<(NN * 32 + TB - 1) / TB, TB>>>();
        k_combine64<<<(NN * 16 + TB - 1) / TB, TB>>>(b1);
    }

    // layer 2: tb1 = Lhat(h1); tb2 = 2*Lhat(tb1) - h1; h2 = relu([h1|tb1|tb2]@W2 + b2)
    {
        int g64 = (NN * 16 + TB - 1) / TB;
        k_gather64<<<g64, TB>>>(h1, tb1, nullptr, 1.0f);
        k_gather64<<<g64, TB>>>(tb1, tb2, h1, 2.0f);
        k_gemm3<<<(NN + 127) / 128, TB>>>(W2, b2);
    }

    // mean pool per graph + FC
    k_pool<<<(NN + 127) / 128, TB>>>();
    k_final<<<1, TB>>>(Wfc, bfc, out);
}

// round 9
// speedup vs baseline: 4.2450x; 1.0857x over previous
#include <cuda_runtime.h>
#include <cuda_fp16.h>
#include <mma.h>
#include <cstddef>

using namespace nvcuda;

#define NN 100000
#define NE 3200000
#define NG 256
#define DIN 128
#define DH 64

// ---------------- scratch (device globals; no allocation) ----------------
__device__ float  g_deg[NN];
__device__ float  g_dinv[NN];
__device__ int    g_src[NE];
__device__ int    g_dst[NE];
__device__ int    g_indeg[NN];
__device__ int    g_rowstart[NN];
__device__ int    g_fill[NN];
__device__ int    g_alloc;
__device__ int2   g_csr[NE];          // {src, bitcast(fp32 weight)}
__device__ int    g_batch[NN];
__device__ int    g_gstart[NG];
__device__ int    g_gend[NG];
__device__ int    g_flags[2];
__device__ float  g_wcat[DIN * 192];  // [W0-W2 | W1 | W2] for layer 1
// fp16 storage (uint2 = 4 halves, 8B aligned)
__device__ uint2  g_P[(size_t)NN * 48];   // x @ wcat, 192 halves/row
__device__ uint2  g_Q[(size_t)NN * 32];   // Lhat(P[:,64:192]), 128 halves/row
__device__ uint2  g_h1[(size_t)NN * 16];  // 64 halves/row
__device__ uint2  g_tb1[(size_t)NN * 16];
__device__ uint2  g_tb2[(size_t)NN * 16];
__device__ float4 g_h2[(size_t)NN * 16];  // fp32 (pool input)
__device__ float  g_gsum[NG * DH];

// ---------------- fp16 pack/unpack ----------------
__device__ __forceinline__ float4 ld_h4(const uint2* p) {
    uint2 u = *p;
    __half2 h0 = *reinterpret_cast<__half2*>(&u.x);
    __half2 h1 = *reinterpret_cast<__half2*>(&u.y);
    float2 f0 = __half22float2(h0), f1 = __half22float2(h1);
    return make_float4(f0.x, f0.y, f1.x, f1.y);
}
__device__ __forceinline__ uint2 st_h4(float4 v) {
    __half2 h0 = __floats2half2_rn(v.x, v.y);
    __half2 h1 = __floats2half2_rn(v.z, v.w);
    uint2 u;
    u.x = *reinterpret_cast<unsigned*>(&h0);
    u.y = *reinterpret_cast<unsigned*>(&h1);
    return u;
}

// ---------------- dtype probe ----------------
__global__ void k_detect(const int* __restrict__ ei_raw, const int* __restrict__ batch_raw) {
    __shared__ int s_ei, s_b;
    int t = threadIdx.x;
    if (t == 0) { s_ei = 0; s_b = 0; }
    __syncthreads();
    int acc_e = 0, acc_b = 0;
    for (int k = t; k < 4096; k += blockDim.x) acc_e |= ei_raw[2 * k + 1];
    for (int k = t; k < 4096; k += blockDim.x) acc_b |= batch_raw[2 * k + 1];
    atomicOr(&s_ei, acc_e);
    atomicOr(&s_b, acc_b);
    __syncthreads();
    if (t == 0) {
        g_flags[0] = (s_ei == 0) ? 1 : 0;
        g_flags[1] = (s_b == 0) ? 1 : 0;
    }
}

// ---------------- prep (main stream) ----------------
__global__ void k_zero_small() {
    int i = blockIdx.x * blockDim.x + threadIdx.x;
    if (i < NN) { g_deg[i] = 0.f; g_indeg[i] = 0; g_fill[i] = 0; }
    if (i < NG * DH) g_gsum[i] = 0.f;
    if (i == 0) g_alloc = 0;
}

__global__ void k_deg_prep(const void* __restrict__ ei_raw) {
    int t = blockIdx.x * blockDim.x + threadIdx.x;
    int e = t * 2;
    if (e >= NE) return;
    int s0, s1, d0, d1;
    if (g_flags[0]) {
        longlong2 sp = ((const longlong2*)ei_raw)[t];
        longlong2 dp = ((const longlong2*)((const long long*)ei_raw + NE))[t];
        s0 = (int)sp.x; s1 = (int)sp.y;
        d0 = (int)dp.x; d1 = (int)dp.y;
    } else {
        int2 sp = ((const int2*)ei_raw)[t];
        int2 dp = ((const int2*)((const int*)ei_raw + NE))[t];
        s0 = sp.x; s1 = sp.y;
        d0 = dp.x; d1 = dp.y;
    }
    s0 = min(max(s0, 0), NN - 1); s1 = min(max(s1, 0), NN - 1);
    d0 = min(max(d0, 0), NN - 1); d1 = min(max(d1, 0), NN - 1);
    g_src[e] = s0; g_src[e + 1] = s1;
    g_dst[e] = d0; g_dst[e + 1] = d1;
    atomicAdd(&g_deg[s0], 1.0f);
    atomicAdd(&g_deg[s1], 1.0f);
    atomicAdd(&g_indeg[d0], 1);
    atomicAdd(&g_indeg[d1], 1);
}

// ---------------- prep (side stream) ----------------
// zeroes gstart/gend itself (side-stream-local; avoids race with k_zero_small)
__global__ void k_batch_prep(const void* __restrict__ batch_raw) {
    int i = blockIdx.x * blockDim.x + threadIdx.x;
    if (i < NG) { g_gstart[i] = 0; g_gend[i] = 0; }
    if (i >= NN) return;
    int b;
    if (g_flags[1]) b = (int)((const long long*)batch_raw)[i];
    else            b = ((const int*)batch_raw)[i];
    g_batch[i] = min(max(b, 0), NG - 1);
}

__global__ void k_bounds() {
    int i = blockIdx.x * blockDim.x + threadIdx.x;
    if (i >= NN) return;
    int b = g_batch[i];
    if (i == 0 || g_batch[i - 1] != b) g_gstart[b] = i;
    if (i == NN - 1 || g_batch[i + 1] != b) g_gend[b] = i + 1;
}

// dinv + CSR row allocation (warp-scan, one atomicAdd per warp)
__global__ void k_alloc() {
    int i = blockIdx.x * blockDim.x + threadIdx.x;
    int lane = threadIdx.x & 31;
    if (i < NN) {
        float d = g_deg[i];
        g_dinv[i] = (d > 0.f) ? rsqrtf(d) : 0.f;
    }
    int v = (i < NN) ? g_indeg[i] : 0;
    int s = v;
#pragma unroll
    for (int o = 1; o < 32; o <<= 1) {
        int t = __shfl_up_sync(0xFFFFFFFF, s, o);
        if (lane >= o) s += t;
    }
    int total = __shfl_sync(0xFFFFFFFF, s, 31);
    int base = 0;
    if (lane == 31) base = atomicAdd(&g_alloc, total);
    base = __shfl_sync(0xFFFFFFFF, base, 31);
    if (i < NN) g_rowstart[i] = base + s - v;
}

__global__ void k_fill() {
    int e = blockIdx.x * blockDim.x + threadIdx.x;
    if (e >= NE) return;
    int s = g_src[e], d = g_dst[e];
    float w = -g_dinv[s] * g_dinv[d];
    int pos = atomicAdd(&g_fill[d], 1);
    int2 ent;
    ent.x = s;
    ent.y = __float_as_int(w);
    g_csr[g_rowstart[d] + pos] = ent;
}

// build Wcat = [W0-W2 | W1 | W2] (128 x 192)
__global__ void k_wcat(const float* __restrict__ W1) {
    int t = blockIdx.x * blockDim.x + threadIdx.x;
    if (t >= DIN * 192) return;
    int i = t / 192, o = t % 192;
    float v;
    if (o < 64)       v = W1[i * 64 + o] - W1[2 * 8192 + i * 64 + o];
    else if (o < 128) v = W1[8192 + i * 64 + (o - 64)];
    else              v = W1[2 * 8192 + i * 64 + (o - 128)];
    g_wcat[t] = v;
}

// ---------------- tensor-core GEMM 1: P = x @ Wcat ----------------
__global__ void k_gemm_p(const float4* __restrict__ A4) {
    __shared__ __align__(32) __half sA[128 * 40];
    __shared__ __align__(32) __half sB[32 * 72];
    __shared__ __align__(32) float  sC[128 * 64];
    const int tid = threadIdx.x;
    const int m0 = blockIdx.x * 128;
    const int n0 = blockIdx.y * 64;
    const int wid = tid >> 5;
    const int wm = wid & 3, wn = wid >> 2;

    wmma::fragment<wmma::accumulator, 16, 16, 16, float> c[2][2];
#pragma unroll
    for (int i = 0; i < 2; i++)
#pragma unroll
        for (int j = 0; j < 2; j++) wmma::fill_fragment(c[i][j], 0.f);

    const int arow = tid >> 1, aseg = tid & 1;
    const int brow = tid >> 3, bc8 = (tid & 7) * 8;

    for (int k0 = 0; k0 < 128; k0 += 32) {
        __syncthreads();
        {
            int gm = m0 + arow;
            uint2* dst = reinterpret_cast<uint2*>(sA) + arow * 10 + aseg * 4;
            if (gm < NN) {
                const float4* src = A4 + (size_t)gm * 32 + (k0 >> 2) + aseg * 4;
#pragma unroll
                for (int q = 0; q < 4; q++) dst[q] = st_h4(src[q]);
            } else {
                uint2 z = make_uint2(0u, 0u);
#pragma unroll
                for (int q = 0; q < 4; q++) dst[q] = z;
            }
        }
        {
            const float4* src = (const float4*)(g_wcat + (size_t)(k0 + brow) * 192 + n0 + bc8);
            uint2* dst = reinterpret_cast<uint2*>(sB) + brow * 18 + (tid & 7) * 2;
            dst[0] = st_h4(src[0]);
            dst[1] = st_h4(src[1]);
        }
        __syncthreads();
#pragma unroll
        for (int kk = 0; kk < 32; kk += 16) {
            wmma::fragment<wmma::matrix_a, 16, 16, 16, __half, wmma::row_major> a[2];
            wmma::fragment<wmma::matrix_b, 16, 16, 16, __half, wmma::row_major> b[2];
#pragma unroll
            for (int i = 0; i < 2; i++)
                wmma::load_matrix_sync(a[i], sA + (wm * 32 + i * 16) * 40 + kk, 40);
#pragma unroll
            for (int j = 0; j < 2; j++)
                wmma::load_matrix_sync(b[j], sB + kk * 72 + wn * 32 + j * 16, 72);
#pragma unroll
            for (int i = 0; i < 2; i++)
#pragma unroll
                for (int j = 0; j < 2; j++) wmma::mma_sync(c[i][j], a[i], b[j], c[i][j]);
        }
    }
#pragma unroll
    for (int i = 0; i < 2; i++)
#pragma unroll
        for (int j = 0; j < 2; j++)
            wmma::store_matrix_sync(sC + (wm * 32 + i * 16) * 64 + wn * 32 + j * 16,
                                    c[i][j], 64, wmma::mem_row_major);
    __syncthreads();
    {
        int row = tid >> 1, seg = tid & 1;
        int gm = m0 + row;
        if (gm < NN) {
            const float* src = sC + row * 64 + seg * 32;
            uint2* dst = g_P + (size_t)gm * 48 + (n0 >> 2) + seg * 8;
#pragma unroll
            for (int q = 0; q < 8; q++)
                dst[q] = st_h4(make_float4(src[q * 4], src[q * 4 + 1], src[q * 4 + 2], src[q * 4 + 3]));
        }
    }
}

// ---------------- gathers (fp16 in, fp32 accumulate; 8-deep MLP) ----------------
__global__ void k_gather128q() {
    int g = blockIdx.x * blockDim.x + threadIdx.x;
    int node = g >> 5;
    if (node >= NN) return;
    int lane = g & 31;
    int start = g_rowstart[node];
    int cnt = g_indeg[node];
    float4 acc = make_float4(0.f, 0.f, 0.f, 0.f);
    const int2* cs = g_csr + start;
    int j = 0;
    for (; j + 8 <= cnt; j += 8) {
        int2 e[8];
        float4 v[8];
#pragma unroll
        for (int u = 0; u < 8; u++) e[u] = cs[j + u];
#pragma unroll
        for (int u = 0; u < 8; u++) v[u] = ld_h4(g_P + (size_t)e[u].x * 48 + 16 + lane);
#pragma unroll
        for (int u = 0; u < 8; u++) {
            float w = __int_as_float(e[u].y);
            acc.x += w * v[u].x; acc.y += w * v[u].y;
            acc.z += w * v[u].z; acc.w += w * v[u].w;
        }
    }
    for (; j < cnt; j++) {
        int2 e0 = cs[j];
        float4 v0 = ld_h4(g_P + (size_t)e0.x * 48 + 16 + lane);
        float w0 = __int_as_float(e0.y);
        acc.x += w0 * v0.x; acc.y += w0 * v0.y; acc.z += w0 * v0.z; acc.w += w0 * v0.w;
    }
    g_Q[(size_t)node * 32 + lane] = st_h4(acc);
}

__global__ void k_combine64(const float* __restrict__ b1) {
    int g = blockIdx.x * blockDim.x + threadIdx.x;
    int node = g >> 4;
    if (node >= NN) return;
    int lane = g & 15;
    int start = g_rowstart[node];
    int cnt = g_indeg[node];
    float4 p = ld_h4(g_P + (size_t)node * 48 + lane);
    float4 q = ld_h4(g_Q + (size_t)node * 32 + lane);
    float4 bb = *(const float4*)(b1 + lane * 4);
    float4 acc = make_float4(p.x + q.x + bb.x, p.y + q.y + bb.y,
                             p.z + q.z + bb.z, p.w + q.w + bb.w);
    const int2* cs = g_csr + start;
    int j = 0;
    for (; j + 8 <= cnt; j += 8) {
        int2 e[8];
        float4 v[8];
#pragma unroll
        for (int u = 0; u < 8; u++) e[u] = cs[j + u];
#pragma unroll
        for (int u = 0; u < 8; u++) v[u] = ld_h4(g_Q + (size_t)e[u].x * 32 + 16 + lane);
#pragma unroll
        for (int u = 0; u < 8; u++) {
            float w = 2.f * __int_as_float(e[u].y);
            acc.x += w * v[u].x; acc.y += w * v[u].y;
            acc.z += w * v[u].z; acc.w += w * v[u].w;
        }
    }
    for (; j < cnt; j++) {
        int2 e0 = cs[j];
        float4 v0 = ld_h4(g_Q + (size_t)e0.x * 32 + 16 + lane);
        float w0 = 2.f * __int_as_float(e0.y);
        acc.x += w0 * v0.x; acc.y += w0 * v0.y; acc.z += w0 * v0.z; acc.w += w0 * v0.w;
    }
    acc.x = fmaxf(acc.x, 0.f); acc.y = fmaxf(acc.y, 0.f);
    acc.z = fmaxf(acc.z, 0.f); acc.w = fmaxf(acc.w, 0.f);
    g_h1[(size_t)node * 16 + lane] = st_h4(acc);
}

__global__ void k_gather64(const uint2* __restrict__ in, uint2* __restrict__ out,
                           const uint2* __restrict__ subsrc, float scale) {
    int g = blockIdx.x * blockDim.x + threadIdx.x;
    int node = g >> 4;
    if (node >= NN) return;
    int lane = g & 15;
    int start = g_rowstart[node];
    int cnt = g_indeg[node];
    float4 acc;
    if (subsrc) {
        float4 t = ld_h4(subsrc + (size_t)node * 16 + lane);
        acc = make_float4(-t.x, -t.y, -t.z, -t.w);
    } else {
        acc = make_float4(0.f, 0.f, 0.f, 0.f);
    }
    const int2* cs = g_csr + start;
    int j = 0;
    for (; j + 8 <= cnt; j += 8) {
        int2 e[8];
        float4 v[8];
#pragma unroll
        for (int u = 0; u < 8; u++) e[u] = cs[j + u];
#pragma unroll
        for (int u = 0; u < 8; u++) v[u] = ld_h4(in + (size_t)e[u].x * 16 + lane);
#pragma unroll
        for (int u = 0; u < 8; u++) {
            float w = __int_as_float(e[u].y) * scale;
            acc.x += w * v[u].x; acc.y += w * v[u].y;
            acc.z += w * v[u].z; acc.w += w * v[u].w;
        }
    }
    for (; j < cnt; j++) {
        int2 e0 = cs[j];
        float4 v0 = ld_h4(in + (size_t)e0.x * 16 + lane);
        float w0 = __int_as_float(e0.y) * scale;
        acc.x += w0 * v0.x; acc.y += w0 * v0.y; acc.z += w0 * v0.z; acc.w += w0 * v0.w;
    }
    out[(size_t)node * 16 + lane] = st_h4(acc);
}

// ---------------- tensor-core GEMM 2: h2 = relu([h1|tb1|tb2] @ W2 + b2) ----------------
__global__ void k_gemm3(const float* __restrict__ W, const float* __restrict__ bias) {
    __shared__ __align__(32) __half sA[128 * 40];
    __shared__ __align__(32) __half sB[32 * 72];
    __shared__ __align__(32) float  sC[128 * 64];
    const int tid = threadIdx.x;
    const int m0 = blockIdx.x * 128;
    const int wid = tid >> 5;
    const int wm = wid & 3, wn = wid >> 2;

    wmma::fragment<wmma::accumulator, 16, 16, 16, float> c[2][2];
#pragma unroll
    for (int i = 0; i < 2; i++)
#pragma unroll
        for (int j = 0; j < 2; j++) wmma::fill_fragment(c[i][j], 0.f);

    const int arow = tid >> 1, aseg = tid & 1;
    const int brow = tid >> 3, bc8 = (tid & 7) * 8;

    for (int k0 = 0; k0 < 192; k0 += 32) {
        const uint2* Asrc = (k0 < 64) ? g_h1 : (k0 < 128 ? g_tb1 : g_tb2);
        const int koff = (k0 & 63) >> 2;
        __syncthreads();
        {
            int gm = m0 + arow;
            uint2* dst = reinterpret_cast<uint2*>(sA) + arow * 10 + aseg * 4;
            if (gm < NN) {
                const uint2* src = Asrc + (size_t)gm * 16 + koff + aseg * 4;
#pragma unroll
                for (int q = 0; q < 4; q++) dst[q] = src[q];
            } else {
                uint2 z = make_uint2(0u, 0u);
#pragma unroll
                for (int q = 0; q < 4; q++) dst[q] = z;
            }
        }
        {
            const float4* src = (const float4*)(W + (size_t)(k0 + brow) * 64 + bc8);
            uint2* dst = reinterpret_cast<uint2*>(sB) + brow * 18 + (tid & 7) * 2;
            dst[0] = st_h4(src[0]);
            dst[1] = st_h4(src[1]);
        }
        __syncthreads();
#pragma unroll
        for (int kk = 0; kk < 32; kk += 16) {
            wmma::fragment<wmma::matrix_a, 16, 16, 16, __half, wmma::row_major> a[2];
            wmma::fragment<wmma::matrix_b, 16, 16, 16, __half, wmma::row_major> b[2];
#pragma unroll
            for (int i = 0; i < 2; i++)
                wmma::load_matrix_sync(a[i], sA + (wm * 32 + i * 16) * 40 + kk, 40);
#pragma unroll
            for (int j = 0; j < 2; j++)
                wmma::load_matrix_sync(b[j], sB + kk * 72 + wn * 32 + j * 16, 72);
#pragma unroll
            for (int i = 0; i < 2; i++)
#pragma unroll
                for (int j = 0; j < 2; j++) wmma::mma_sync(c[i][j], a[i], b[j], c[i][j]);
        }
    }
#pragma unroll
    for (int i = 0; i < 2; i++)
#pragma unroll
        for (int j = 0; j < 2; j++)
            wmma::store_matrix_sync(sC + (wm * 32 + i * 16) * 64 + wn * 32 + j * 16,
                                    c[i][j], 64, wmma::mem_row_major);
    __syncthreads();
    {
        int row = tid >> 1, seg = tid & 1;
        int gm = m0 + row;
        if (gm < NN) {
            const float* src = sC + row * 64 + seg * 32;
#pragma unroll
            for (int q = 0; q < 8; q++) {
                float4 bb = *(const float4*)(bias + seg * 32 + q * 4);
                float4 o;
                o.x = fmaxf(src[q * 4 + 0] + bb.x, 0.f);
                o.y = fmaxf(src[q * 4 + 1] + bb.y, 0.f);
                o.z = fmaxf(src[q * 4 + 2] + bb.z, 0.f);
                o.w = fmaxf(src[q * 4 + 3] + bb.w, 0.f);
                g_h2[(size_t)gm * 16 + seg * 8 + q] = o;
            }
        }
    }
}

// ---------------- pooling + FC ----------------
__global__ void k_pool() {
    int col = threadIdx.x & 63;
    int sub = threadIdx.x >> 6;
    int n0 = blockIdx.x * 128 + sub * 32;
    const float* h = (const float*)g_h2;
    float acc = 0.f;
    int cur = -1;
    for (int k = 0; k < 32; k++) {
        int n = n0 + k;
        if (n >= NN) break;
        int gph = g_batch[n];
        if (gph != cur) {
            if (cur >= 0) atomicAdd(&g_gsum[cur * 64 + col], acc);
            cur = gph;
            acc = 0.f;
        }
        acc += h[(size_t)n * 64 + col];
    }
    if (cur >= 0) atomicAdd(&g_gsum[cur * 64 + col], acc);
}

__global__ void k_final(const float* __restrict__ Wfc, const float* __restrict__ bfc,
                        float* __restrict__ out) {
    int gph = threadIdx.x;
    if (gph < NG) {
        float c = fmaxf((float)(g_gend[gph] - g_gstart[gph]), 1.0f);
        float s = 0.f;
#pragma unroll
        for (int o = 0; o < 64; o++) s += g_gsum[gph * 64 + o] * Wfc[o];
        out[gph] = s / c + bfc[0];
    }
}

// ---------------- launch ----------------
extern "C" void kernel_launch(void* const* d_in, const int* in_sizes, int n_in,
                              void* d_out, int out_size) {
    const float *x = nullptr, *W1 = nullptr, *b1 = nullptr, *W2 = nullptr,
                *b2 = nullptr, *Wfc = nullptr, *bfc = nullptr;
    const void *ei = nullptr, *batch = nullptr;
    int idx64[3] = {-1, -1, -1};
    int n64 = 0, idxW2 = -1;
    for (int i = 0; i < n_in; i++) {
        int s = in_sizes[i];
        switch (s) {
            case 12800000: x = (const float*)d_in[i]; break;
            case 6400000:  ei = d_in[i]; break;
            case 100000:   batch = d_in[i]; break;
            case 24576:    W1 = (const float*)d_in[i]; break;
            case 12288:    W2 = (const float*)d_in[i]; idxW2 = i; break;
            case 1:        bfc = (const float*)d_in[i]; break;
            case 64:       if (n64 < 3) idx64[n64++] = i; break;
            default: break;
        }
    }
    if (n64 == 3) {
        if (idx64[0] < idxW2) {
            b1 = (const float*)d_in[idx64[0]];
            b2 = (const float*)d_in[idx64[1]];
            Wfc = (const float*)d_in[idx64[2]];
        } else {
            Wfc = (const float*)d_in[idx64[0]];
            b1 = (const float*)d_in[idx64[1]];
            b2 = (const float*)d_in[idx64[2]];
        }
    }
    float* out = (float*)d_out;

    uint2 *h1, *tb1, *tb2;
    cudaGetSymbolAddress((void**)&h1, g_h1);
    cudaGetSymbolAddress((void**)&tb1, g_tb1);
    cudaGetSymbolAddress((void**)&tb2, g_tb2);

    // side stream + fork/join events, created once on the (uncaptured)
    // correctness call, reused identically every call.
    static cudaStream_t s_side = nullptr;
    static cudaEvent_t s_fork = nullptr, s_join = nullptr;
    if (!s_side) {
        cudaStreamCreateWithFlags(&s_side, cudaStreamNonBlocking);
        cudaEventCreateWithFlags(&s_fork, cudaEventDisableTiming);
        cudaEventCreateWithFlags(&s_join, cudaEventDisableTiming);
    }

    const int TB = 256;

    // fork: side stream handles layer-1 GEMM + batch bookkeeping
    cudaEventRecord(s_fork, 0);
    cudaStreamWaitEvent(s_side, s_fork, 0);
    {
        dim3 gp((NN + 127) / 128, 3);
        k_wcat<<<(DIN * 192 + TB - 1) / TB, TB, 0, s_side>>>(W1);
        k_gemm_p<<<gp, TB, 0, s_side>>>((const float4*)x);
        k_batch_prep<<<(NN + TB - 1) / TB, TB, 0, s_side>>>(batch);
        k_bounds<<<(NN + TB - 1) / TB, TB, 0, s_side>>>();
        cudaEventRecord(s_join, s_side);
    }

    // main stream: CSR build
    k_detect<<<1, 256>>>((const int*)ei, (const int*)batch);
    k_zero_small<<<(NN + TB - 1) / TB, TB>>>();
    k_deg_prep<<<(NE / 2 + TB - 1) / TB, TB>>>(ei);
    k_alloc<<<(NN + TB - 1) / TB, TB>>>();
    k_fill<<<(NE + TB - 1) / TB, TB>>>();

    // join: gathers need both P (side) and CSR (main)
    cudaStreamWaitEvent(0, s_join, 0);

    // layer 1 gathers: Q = Lhat(P[:,64:192]); h1 = relu(P0 + Q1 + 2*Lhat(Q2) + b1)
    k_gather128q<<<(NN * 32 + TB - 1) / TB, TB>>>();
    k_combine64<<<(NN * 16 + TB - 1) / TB, TB>>>(b1);

    // layer 2
    {
        int g64 = (NN * 16 + TB - 1) / TB;
        k_gather64<<<g64, TB>>>(h1, tb1, nullptr, 1.0f);
        k_gather64<<<g64, TB>>>(tb1, tb2, h1, 2.0f);
        k_gemm3<<<(NN + 127) / 128, TB>>>(W2, b2);
    }

    // mean pool per graph + FC
    k_pool<<<(NN + 127) / 128, TB>>>();
    k_final<<<1, TB>>>(Wfc, bfc, out);
}

// round 10
// speedup vs baseline: 4.4655x; 1.0519x over previous
#include <cuda_runtime.h>
#include <cuda_fp16.h>
#include <mma.h>
#include <cstddef>

using namespace nvcuda;

#define NN 100000
#define NE 3200000
#define NG 256
#define DIN 128
#define DH 64

// ---------------- scratch (device globals; no allocation) ----------------
__device__ float  g_deg[NN];
__device__ float  g_dinv[NN];
__device__ int    g_indeg[NN];
__device__ int    g_rowstart[NN];
__device__ int    g_fill[NN];
__device__ int    g_alloc;
__device__ int    g_csri[NE];         // src index only (weights factorized out)
__device__ int    g_batch[NN];
__device__ int    g_gstart[NG];
__device__ int    g_gend[NG];
__device__ int    g_flags[2];
__device__ float  g_wcat[DIN * 192];  // [W0-W2 | W1 | W2] for layer 1
// fp16 storage (uint2 = 4 halves, 8B aligned)
__device__ uint2  g_P[(size_t)NN * 48];   // x @ wcat (unscaled), 192 halves/row
__device__ uint2  g_Q[(size_t)NN * 32];   // lanes 0-15: Q1; lanes 16-31: Q2s = dinv*Q2
__device__ uint2  g_h1[(size_t)NN * 16];
__device__ uint2  g_h1s[(size_t)NN * 16]; // dinv * h1
__device__ uint2  g_tb1[(size_t)NN * 16];
__device__ uint2  g_tb1s[(size_t)NN * 16];
__device__ uint2  g_tb2[(size_t)NN * 16];
__device__ uint2  g_h2[(size_t)NN * 16];  // fp16 pool input
__device__ float  g_gsum[NG * DH];

// ---------------- fp16 pack/unpack ----------------
__device__ __forceinline__ float4 ld_h4(const uint2* p) {
    uint2 u = *p;
    __half2 h0 = *reinterpret_cast<__half2*>(&u.x);
    __half2 h1 = *reinterpret_cast<__half2*>(&u.y);
    float2 f0 = __half22float2(h0), f1 = __half22float2(h1);
    return make_float4(f0.x, f0.y, f1.x, f1.y);
}
__device__ __forceinline__ uint2 st_h4(float4 v) {
    __half2 h0 = __floats2half2_rn(v.x, v.y);
    __half2 h1 = __floats2half2_rn(v.z, v.w);
    uint2 u;
    u.x = *reinterpret_cast<unsigned*>(&h0);
    u.y = *reinterpret_cast<unsigned*>(&h1);
    return u;
}

// ---------------- dtype probe (must finish before the stream fork) ----------------
__global__ void k_detect(const int* __restrict__ ei_raw, const int* __restrict__ batch_raw) {
    __shared__ int s_ei, s_b;
    int t = threadIdx.x;
    if (t == 0) { s_ei = 0; s_b = 0; }
    __syncthreads();
    int acc_e = 0, acc_b = 0;
    for (int k = t; k < 4096; k += blockDim.x) acc_e |= ei_raw[2 * k + 1];
    for (int k = t; k < 4096; k += blockDim.x) acc_b |= batch_raw[2 * k + 1];
    atomicOr(&s_ei, acc_e);
    atomicOr(&s_b, acc_b);
    __syncthreads();
    if (t == 0) {
        g_flags[0] = (s_ei == 0) ? 1 : 0;
        g_flags[1] = (s_b == 0) ? 1 : 0;
    }
}

// ---------------- prep (main stream) ----------------
__global__ void k_zero_small() {
    int i = blockIdx.x * blockDim.x + threadIdx.x;
    if (i < NN) { g_deg[i] = 0.f; g_indeg[i] = 0; g_fill[i] = 0; }
    if (i < NG * DH) g_gsum[i] = 0.f;
    if (i == 0) g_alloc = 0;
}

__global__ void k_deg_prep(const void* __restrict__ ei_raw) {
    int t = blockIdx.x * blockDim.x + threadIdx.x;
    int e = t * 2;
    if (e >= NE) return;
    int s0, s1, d0, d1;
    if (g_flags[0]) {
        longlong2 sp = ((const longlong2*)ei_raw)[t];
        longlong2 dp = ((const longlong2*)((const long long*)ei_raw + NE))[t];
        s0 = (int)sp.x; s1 = (int)sp.y;
        d0 = (int)dp.x; d1 = (int)dp.y;
    } else {
        int2 sp = ((const int2*)ei_raw)[t];
        int2 dp = ((const int2*)((const int*)ei_raw + NE))[t];
        s0 = sp.x; s1 = sp.y;
        d0 = dp.x; d1 = dp.y;
    }
    s0 = min(max(s0, 0), NN - 1); s1 = min(max(s1, 0), NN - 1);
    d0 = min(max(d0, 0), NN - 1); d1 = min(max(d1, 0), NN - 1);
    atomicAdd(&g_deg[s0], 1.0f);
    atomicAdd(&g_deg[s1], 1.0f);
    atomicAdd(&g_indeg[d0], 1);
    atomicAdd(&g_indeg[d1], 1);
}

// dinv + CSR row allocation (warp-scan, one atomicAdd per warp)
__global__ void k_alloc() {
    int i = blockIdx.x * blockDim.x + threadIdx.x;
    int lane = threadIdx.x & 31;
    if (i < NN) {
        float d = g_deg[i];
        g_dinv[i] = (d > 0.f) ? rsqrtf(d) : 0.f;
    }
    int v = (i < NN) ? g_indeg[i] : 0;
    int s = v;
#pragma unroll
    for (int o = 1; o < 32; o <<= 1) {
        int t = __shfl_up_sync(0xFFFFFFFF, s, o);
        if (lane >= o) s += t;
    }
    int total = __shfl_sync(0xFFFFFFFF, s, 31);
    int base = 0;
    if (lane == 31) base = atomicAdd(&g_alloc, total);
    base = __shfl_sync(0xFFFFFFFF, base, 31);
    if (i < NN) g_rowstart[i] = base + s - v;
}

// fill CSR (src only) by re-decoding edge_index (L2-hot from k_deg_prep)
__global__ void k_fill(const void* __restrict__ ei_raw) {
    int e = blockIdx.x * blockDim.x + threadIdx.x;
    if (e >= NE) return;
    int s, d;
    if (g_flags[0]) {
        const long long* p = (const long long*)ei_raw;
        s = (int)p[e];
        d = (int)p[NE + e];
    } else {
        const int* p = (const int*)ei_raw;
        s = p[e];
        d = p[NE + e];
    }
    s = min(max(s, 0), NN - 1);
    d = min(max(d, 0), NN - 1);
    int pos = atomicAdd(&g_fill[d], 1);
    g_csri[g_rowstart[d] + pos] = s;
}

// ---------------- prep (side stream) ----------------
__global__ void k_batch_prep(const void* __restrict__ batch_raw) {
    int i = blockIdx.x * blockDim.x + threadIdx.x;
    if (i < NG) { g_gstart[i] = 0; g_gend[i] = 0; }
    if (i >= NN) return;
    int b;
    if (g_flags[1]) b = (int)((const long long*)batch_raw)[i];
    else            b = ((const int*)batch_raw)[i];
    g_batch[i] = min(max(b, 0), NG - 1);
}

__global__ void k_bounds() {
    int i = blockIdx.x * blockDim.x + threadIdx.x;
    if (i >= NN) return;
    int b = g_batch[i];
    if (i == 0 || g_batch[i - 1] != b) g_gstart[b] = i;
    if (i == NN - 1 || g_batch[i + 1] != b) g_gend[b] = i + 1;
}

// build Wcat = [W0-W2 | W1 | W2] (128 x 192)
__global__ void k_wcat(const float* __restrict__ W1) {
    int t = blockIdx.x * blockDim.x + threadIdx.x;
    if (t >= DIN * 192) return;
    int i = t / 192, o = t % 192;
    float v;
    if (o < 64)       v = W1[i * 64 + o] - W1[2 * 8192 + i * 64 + o];
    else if (o < 128) v = W1[8192 + i * 64 + (o - 64)];
    else              v = W1[2 * 8192 + i * 64 + (o - 128)];
    g_wcat[t] = v;
}

// ---------------- tensor-core GEMM 1: P = x @ Wcat (unscaled) ----------------
__global__ void k_gemm_p(const float4* __restrict__ A4) {
    __shared__ __align__(32) __half sA[128 * 40];
    __shared__ __align__(32) __half sB[32 * 72];
    __shared__ __align__(32) float  sC[128 * 64];
    const int tid = threadIdx.x;
    const int m0 = blockIdx.x * 128;
    const int n0 = blockIdx.y * 64;
    const int wid = tid >> 5;
    const int wm = wid & 3, wn = wid >> 2;

    wmma::fragment<wmma::accumulator, 16, 16, 16, float> c[2][2];
#pragma unroll
    for (int i = 0; i < 2; i++)
#pragma unroll
        for (int j = 0; j < 2; j++) wmma::fill_fragment(c[i][j], 0.f);

    const int arow = tid >> 1, aseg = tid & 1;
    const int brow = tid >> 3, bc8 = (tid & 7) * 8;

    for (int k0 = 0; k0 < 128; k0 += 32) {
        __syncthreads();
        {
            int gm = m0 + arow;
            uint2* dst = reinterpret_cast<uint2*>(sA) + arow * 10 + aseg * 4;
            if (gm < NN) {
                const float4* src = A4 + (size_t)gm * 32 + (k0 >> 2) + aseg * 4;
#pragma unroll
                for (int q = 0; q < 4; q++) dst[q] = st_h4(src[q]);
            } else {
                uint2 z = make_uint2(0u, 0u);
#pragma unroll
                for (int q = 0; q < 4; q++) dst[q] = z;
            }
        }
        {
            const float4* src = (const float4*)(g_wcat + (size_t)(k0 + brow) * 192 + n0 + bc8);
            uint2* dst = reinterpret_cast<uint2*>(sB) + brow * 18 + (tid & 7) * 2;
            dst[0] = st_h4(src[0]);
            dst[1] = st_h4(src[1]);
        }
        __syncthreads();
#pragma unroll
        for (int kk = 0; kk < 32; kk += 16) {
            wmma::fragment<wmma::matrix_a, 16, 16, 16, __half, wmma::row_major> a[2];
            wmma::fragment<wmma::matrix_b, 16, 16, 16, __half, wmma::row_major> b[2];
#pragma unroll
            for (int i = 0; i < 2; i++)
                wmma::load_matrix_sync(a[i], sA + (wm * 32 + i * 16) * 40 + kk, 40);
#pragma unroll
            for (int j = 0; j < 2; j++)
                wmma::load_matrix_sync(b[j], sB + kk * 72 + wn * 32 + j * 16, 72);
#pragma unroll
            for (int i = 0; i < 2; i++)
#pragma unroll
                for (int j = 0; j < 2; j++) wmma::mma_sync(c[i][j], a[i], b[j], c[i][j]);
        }
    }
#pragma unroll
    for (int i = 0; i < 2; i++)
#pragma unroll
        for (int j = 0; j < 2; j++)
            wmma::store_matrix_sync(sC + (wm * 32 + i * 16) * 64 + wn * 32 + j * 16,
                                    c[i][j], 64, wmma::mem_row_major);
    __syncthreads();
    {
        int row = tid >> 1, seg = tid & 1;
        int gm = m0 + row;
        if (gm < NN) {
            const float* src = sC + row * 64 + seg * 32;
            uint2* dst = g_P + (size_t)gm * 48 + (n0 >> 2) + seg * 8;
#pragma unroll
            for (int q = 0; q < 8; q++)
                dst[q] = st_h4(make_float4(src[q * 4], src[q * 4 + 1], src[q * 4 + 2], src[q * 4 + 3]));
        }
    }
}

// ---------------- gathers (weight-factorized; fp16 in, fp32 accumulate) ----------------
// Q gather: acc = sum dinv[s] * P[s][64:192]; store Q1 = -dv*acc (lanes 0-15),
// Q2s = -dv^2*acc (lanes 16-31).
__global__ void k_gather128q() {
    int g = blockIdx.x * blockDim.x + threadIdx.x;
    int node = g >> 5;
    if (node >= NN) return;
    int lane = g & 31;
    int start = g_rowstart[node];
    int cnt = g_indeg[node];
    float4 acc = make_float4(0.f, 0.f, 0.f, 0.f);
    const int* cs = g_csri + start;
    int j = 0;
    for (; j + 8 <= cnt; j += 8) {
        int e[8];
        float ds[8];
        float4 v[8];
#pragma unroll
        for (int u = 0; u < 8; u++) e[u] = cs[j + u];
#pragma unroll
        for (int u = 0; u < 8; u++) { ds[u] = g_dinv[e[u]]; v[u] = ld_h4(g_P + (size_t)e[u] * 48 + 16 + lane); }
#pragma unroll
        for (int u = 0; u < 8; u++) {
            acc.x += ds[u] * v[u].x; acc.y += ds[u] * v[u].y;
            acc.z += ds[u] * v[u].z; acc.w += ds[u] * v[u].w;
        }
    }
    for (; j < cnt; j++) {
        int e0 = cs[j];
        float d0 = g_dinv[e0];
        float4 v0 = ld_h4(g_P + (size_t)e0 * 48 + 16 + lane);
        acc.x += d0 * v0.x; acc.y += d0 * v0.y; acc.z += d0 * v0.z; acc.w += d0 * v0.w;
    }
    float dv = g_dinv[node];
    float f = (lane < 16) ? -dv : -(dv * dv);
    g_Q[(size_t)node * 32 + lane] = st_h4(make_float4(acc.x * f, acc.y * f, acc.z * f, acc.w * f));
}

// h1 = relu(P0 + Q1 - 2*dv*sum(Q2s) + b1); store h1 and h1s = dv*h1
__global__ void k_combine64(const float* __restrict__ b1) {
    int g = blockIdx.x * blockDim.x + threadIdx.x;
    int node = g >> 4;
    if (node >= NN) return;
    int lane = g & 15;
    int start = g_rowstart[node];
    int cnt = g_indeg[node];
    float4 p = ld_h4(g_P + (size_t)node * 48 + lane);
    float4 q = ld_h4(g_Q + (size_t)node * 32 + lane);
    float4 bb = *(const float4*)(b1 + lane * 4);
    float4 sum = make_float4(0.f, 0.f, 0.f, 0.f);
    const int* cs = g_csri + start;
    int j = 0;
    for (; j + 8 <= cnt; j += 8) {
        int e[8];
        float4 v[8];
#pragma unroll
        for (int u = 0; u < 8; u++) e[u] = cs[j + u];
#pragma unroll
        for (int u = 0; u < 8; u++) v[u] = ld_h4(g_Q + (size_t)e[u] * 32 + 16 + lane);
#pragma unroll
        for (int u = 0; u < 8; u++) {
            sum.x += v[u].x; sum.y += v[u].y; sum.z += v[u].z; sum.w += v[u].w;
        }
    }
    for (; j < cnt; j++) {
        int e0 = cs[j];
        float4 v0 = ld_h4(g_Q + (size_t)e0 * 32 + 16 + lane);
        sum.x += v0.x; sum.y += v0.y; sum.z += v0.z; sum.w += v0.w;
    }
    float dv = g_dinv[node];
    float m = -2.f * dv;
    float4 acc;
    acc.x = fmaxf(p.x + q.x + bb.x + m * sum.x, 0.f);
    acc.y = fmaxf(p.y + q.y + bb.y + m * sum.y, 0.f);
    acc.z = fmaxf(p.z + q.z + bb.z + m * sum.z, 0.f);
    acc.w = fmaxf(p.w + q.w + bb.w + m * sum.w, 0.f);
    g_h1[(size_t)node * 16 + lane] = st_h4(acc);
    g_h1s[(size_t)node * 16 + lane] =
        st_h4(make_float4(dv * acc.x, dv * acc.y, dv * acc.z, dv * acc.w));
}

// generic D=64 factorized gather:
// val = mul*dv*sum(in[s]) - (subsrc? subsrc[node]:0); out = val; outs = dv*val (optional)
__global__ void k_gather64(const uint2* __restrict__ in, uint2* __restrict__ out,
                           uint2* __restrict__ outs, const uint2* __restrict__ subsrc,
                           float mul) {
    int g = blockIdx.x * blockDim.x + threadIdx.x;
    int node = g >> 4;
    if (node >= NN) return;
    int lane = g & 15;
    int start = g_rowstart[node];
    int cnt = g_indeg[node];
    float4 sum = make_float4(0.f, 0.f, 0.f, 0.f);
    const int* cs = g_csri + start;
    int j = 0;
    for (; j + 8 <= cnt; j += 8) {
        int e[8];
        float4 v[8];
#pragma unroll
        for (int u = 0; u < 8; u++) e[u] = cs[j + u];
#pragma unroll
        for (int u = 0; u < 8; u++) v[u] = ld_h4(in + (size_t)e[u] * 16 + lane);
#pragma unroll
        for (int u = 0; u < 8; u++) {
            sum.x += v[u].x; sum.y += v[u].y; sum.z += v[u].z; sum.w += v[u].w;
        }
    }
    for (; j < cnt; j++) {
        int e0 = cs[j];
        float4 v0 = ld_h4(in + (size_t)e0 * 16 + lane);
        sum.x += v0.x; sum.y += v0.y; sum.z += v0.z; sum.w += v0.w;
    }
    float dv = g_dinv[node];
    float m = mul * dv;
    float4 val = make_float4(m * sum.x, m * sum.y, m * sum.z, m * sum.w);
    if (subsrc) {
        float4 t = ld_h4(subsrc + (size_t)node * 16 + lane);
        val.x -= t.x; val.y -= t.y; val.z -= t.z; val.w -= t.w;
    }
    out[(size_t)node * 16 + lane] = st_h4(val);
    if (outs)
        outs[(size_t)node * 16 + lane] =
            st_h4(make_float4(dv * val.x, dv * val.y, dv * val.z, dv * val.w));
}

// ---------------- tensor-core GEMM 2: h2 = relu([h1|tb1|tb2] @ W2 + b2), fp16 out ----------------
__global__ void k_gemm3(const float* __restrict__ W, const float* __restrict__ bias) {
    __shared__ __align__(32) __half sA[128 * 40];
    __shared__ __align__(32) __half sB[32 * 72];
    __shared__ __align__(32) float  sC[128 * 64];
    const int tid = threadIdx.x;
    const int m0 = blockIdx.x * 128;
    const int wid = tid >> 5;
    const int wm = wid & 3, wn = wid >> 2;

    wmma::fragment<wmma::accumulator, 16, 16, 16, float> c[2][2];
#pragma unroll
    for (int i = 0; i < 2; i++)
#pragma unroll
        for (int j = 0; j < 2; j++) wmma::fill_fragment(c[i][j], 0.f);

    const int arow = tid >> 1, aseg = tid & 1;
    const int brow = tid >> 3, bc8 = (tid & 7) * 8;

    for (int k0 = 0; k0 < 192; k0 += 32) {
        const uint2* Asrc = (k0 < 64) ? g_h1 : (k0 < 128 ? g_tb1 : g_tb2);
        const int koff = (k0 & 63) >> 2;
        __syncthreads();
        {
            int gm = m0 + arow;
            uint2* dst = reinterpret_cast<uint2*>(sA) + arow * 10 + aseg * 4;
            if (gm < NN) {
                const uint2* src = Asrc + (size_t)gm * 16 + koff + aseg * 4;
#pragma unroll
                for (int q = 0; q < 4; q++) dst[q] = src[q];
            } else {
                uint2 z = make_uint2(0u, 0u);
#pragma unroll
                for (int q = 0; q < 4; q++) dst[q] = z;
            }
        }
        {
            const float4* src = (const float4*)(W + (size_t)(k0 + brow) * 64 + bc8);
            uint2* dst = reinterpret_cast<uint2*>(sB) + brow * 18 + (tid & 7) * 2;
            dst[0] = st_h4(src[0]);
            dst[1] = st_h4(src[1]);
        }
        __syncthreads();
#pragma unroll
        for (int kk = 0; kk < 32; kk += 16) {
            wmma::fragment<wmma::matrix_a, 16, 16, 16, __half, wmma::row_major> a[2];
            wmma::fragment<wmma::matrix_b, 16, 16, 16, __half, wmma::row_major> b[2];
#pragma unroll
            for (int i = 0; i < 2; i++)
                wmma::load_matrix_sync(a[i], sA + (wm * 32 + i * 16) * 40 + kk, 40);
#pragma unroll
            for (int j = 0; j < 2; j++)
                wmma::load_matrix_sync(b[j], sB + kk * 72 + wn * 32 + j * 16, 72);
#pragma unroll
            for (int i = 0; i < 2; i++)
#pragma unroll
                for (int j = 0; j < 2; j++) wmma::mma_sync(c[i][j], a[i], b[j], c[i][j]);
        }
    }
#pragma unroll
    for (int i = 0; i < 2; i++)
#pragma unroll
        for (int j = 0; j < 2; j++)
            wmma::store_matrix_sync(sC + (wm * 32 + i * 16) * 64 + wn * 32 + j * 16,
                                    c[i][j], 64, wmma::mem_row_major);
    __syncthreads();
    {
        int row = tid >> 1, seg = tid & 1;
        int gm = m0 + row;
        if (gm < NN) {
            const float* src = sC + row * 64 + seg * 32;
#pragma unroll
            for (int q = 0; q < 8; q++) {
                float4 bb = *(const float4*)(bias + seg * 32 + q * 4);
                float4 o;
                o.x = fmaxf(src[q * 4 + 0] + bb.x, 0.f);
                o.y = fmaxf(src[q * 4 + 1] + bb.y, 0.f);
                o.z = fmaxf(src[q * 4 + 2] + bb.z, 0.f);
                o.w = fmaxf(src[q * 4 + 3] + bb.w, 0.f);
                g_h2[(size_t)gm * 16 + seg * 8 + q] = st_h4(o);
            }
        }
    }
}

// ---------------- pooling + FC ----------------
// 256 threads = 16 col-groups (uint2) x 16 subs; each sub scans 32 sorted nodes.
__global__ void k_pool() {
    int col4 = threadIdx.x & 15;
    int sub = threadIdx.x >> 4;
    int n0 = blockIdx.x * 512 + sub * 32;
    float4 acc = make_float4(0.f, 0.f, 0.f, 0.f);
    int cur = -1;
    for (int k = 0; k < 32; k++) {
        int n = n0 + k;
        if (n >= NN) break;
        int gph = g_batch[n];
        if (gph != cur) {
            if (cur >= 0) {
                atomicAdd(&g_gsum[cur * 64 + col4 * 4 + 0], acc.x);
                atomicAdd(&g_gsum[cur * 64 + col4 * 4 + 1], acc.y);
                atomicAdd(&g_gsum[cur * 64 + col4 * 4 + 2], acc.z);
                atomicAdd(&g_gsum[cur * 64 + col4 * 4 + 3], acc.w);
            }
            cur = gph;
            acc = make_float4(0.f, 0.f, 0.f, 0.f);
        }
        float4 v = ld_h4(g_h2 + (size_t)n * 16 + col4);
        acc.x += v.x; acc.y += v.y; acc.z += v.z; acc.w += v.w;
    }
    if (cur >= 0) {
        atomicAdd(&g_gsum[cur * 64 + col4 * 4 + 0], acc.x);
        atomicAdd(&g_gsum[cur * 64 + col4 * 4 + 1], acc.y);
        atomicAdd(&g_gsum[cur * 64 + col4 * 4 + 2], acc.z);
        atomicAdd(&g_gsum[cur * 64 + col4 * 4 + 3], acc.w);
    }
}

__global__ void k_final(const float* __restrict__ Wfc, const float* __restrict__ bfc,
                        float* __restrict__ out) {
    int gph = threadIdx.x;
    if (gph < NG) {
        float c = fmaxf((float)(g_gend[gph] - g_gstart[gph]), 1.0f);
        float s = 0.f;
#pragma unroll
        for (int o = 0; o < 64; o++) s += g_gsum[gph * 64 + o] * Wfc[o];
        out[gph] = s / c + bfc[0];
    }
}

// ---------------- launch ----------------
extern "C" void kernel_launch(void* const* d_in, const int* in_sizes, int n_in,
                              void* d_out, int out_size) {
    const float *x = nullptr, *W1 = nullptr, *b1 = nullptr, *W2 = nullptr,
                *b2 = nullptr, *Wfc = nullptr, *bfc = nullptr;
    const void *ei = nullptr, *batch = nullptr;
    int idx64[3] = {-1, -1, -1};
    int n64 = 0, idxW2 = -1;
    for (int i = 0; i < n_in; i++) {
        int s = in_sizes[i];
        switch (s) {
            case 12800000: x = (const float*)d_in[i]; break;
            case 6400000:  ei = d_in[i]; break;
            case 100000:   batch = d_in[i]; break;
            case 24576:    W1 = (const float*)d_in[i]; break;
            case 12288:    W2 = (const float*)d_in[i]; idxW2 = i; break;
            case 1:        bfc = (const float*)d_in[i]; break;
            case 64:       if (n64 < 3) idx64[n64++] = i; break;
            default: break;
        }
    }
    if (n64 == 3) {
        if (idx64[0] < idxW2) {
            b1 = (const float*)d_in[idx64[0]];
            b2 = (const float*)d_in[idx64[1]];
            Wfc = (const float*)d_in[idx64[2]];
        } else {
            Wfc = (const float*)d_in[idx64[0]];
            b1 = (const float*)d_in[idx64[1]];
            b2 = (const float*)d_in[idx64[2]];
        }
    }
    float* out = (float*)d_out;

    uint2 *h1, *h1s, *tb1, *tb1s, *tb2;
    cudaGetSymbolAddress((void**)&h1, g_h1);
    cudaGetSymbolAddress((void**)&h1s, g_h1s);
    cudaGetSymbolAddress((void**)&tb1, g_tb1);
    cudaGetSymbolAddress((void**)&tb1s, g_tb1s);
    cudaGetSymbolAddress((void**)&tb2, g_tb2);

    static cudaStream_t s_side = nullptr;
    static cudaEvent_t s_fork = nullptr, s_join = nullptr;
    if (!s_side) {
        cudaStreamCreateWithFlags(&s_side, cudaStreamNonBlocking);
        cudaEventCreateWithFlags(&s_fork, cudaEventDisableTiming);
        cudaEventCreateWithFlags(&s_join, cudaEventDisableTiming);
    }

    const int TB = 256;

    // detect FIRST (both streams read g_flags), then fork
    k_detect<<<1, 256>>>((const int*)ei, (const int*)batch);
    cudaEventRecord(s_fork, 0);
    cudaStreamWaitEvent(s_side, s_fork, 0);

    // side stream: layer-1 GEMM + batch bookkeeping
    {
        dim3 gp((NN + 127) / 128, 3);
        k_wcat<<<(DIN * 192 + TB - 1) / TB, TB, 0, s_side>>>(W1);
        k_gemm_p<<<gp, TB, 0, s_side>>>((const float4*)x);
        k_batch_prep<<<(NN + TB - 1) / TB, TB, 0, s_side>>>(batch);
        k_bounds<<<(NN + TB - 1) / TB, TB, 0, s_side>>>();
        cudaEventRecord(s_join, s_side);
    }

    // main stream: CSR build
    k_zero_small<<<(NN + TB - 1) / TB, TB>>>();
    k_deg_prep<<<(NE / 2 + TB - 1) / TB, TB>>>(ei);
    k_alloc<<<(NN + TB - 1) / TB, TB>>>();
    k_fill<<<(NE + TB - 1) / TB, TB>>>(ei);

    cudaStreamWaitEvent(0, s_join, 0);

    // layer 1 gathers
    k_gather128q<<<(NN * 32 + TB - 1) / TB, TB>>>();
    k_combine64<<<(NN * 16 + TB - 1) / TB, TB>>>(b1);

    // layer 2
    {
        int g64 = (NN * 16 + TB - 1) / TB;
        k_gather64<<<g64, TB>>>(h1s, tb1, tb1s, nullptr, -1.0f);
        k_gather64<<<g64, TB>>>(tb1s, tb2, nullptr, h1, -2.0f);
        k_gemm3<<<(NN + 127) / 128, TB>>>(W2, b2);
    }

    // mean pool per graph + FC
    k_pool<<<(NN + 511) / 512, TB>>>();
    k_final<<<1, TB>>>(Wfc, bfc, out);
}

// round 11
// speedup vs baseline: 4.6939x; 1.0511x over previous
#include <cuda_runtime.h>
#include <cuda_fp16.h>
#include <mma.h>
#include <cstddef>

using namespace nvcuda;

#define NN 100000
#define NE 3200000
#define NG 256
#define DIN 128
#define DH 64

// ---------------- scratch (device globals; no allocation) ----------------
__device__ float  g_deg[NN];
__device__ float  g_dinv[NN];
__device__ int    g_indeg[NN];
__device__ int    g_rowstart[NN];
__device__ int    g_fill[NN];
__device__ int    g_alloc;
__device__ int    g_csri[NE];         // src index only (weights factorized out)
__device__ int    g_batch[NN];
__device__ int    g_gstart[NG];
__device__ int    g_gend[NG];
__device__ int    g_flags[2];
__device__ float  g_wcat[DIN * 192];  // [W0-W2 | W1 | W2] for layer 1
// fp16 storage (uint2 = 4 halves, 8B aligned)
__device__ uint2  g_P[(size_t)NN * 48];    // x @ wcat: P0|P1|P2, 192 halves/row
__device__ uint2  g_Rsc[(size_t)NN * 16];  // dinv*(P1 + 2*Lhat(P2)), 64 halves/row
__device__ uint2  g_h1[(size_t)NN * 16];
__device__ uint2  g_h1s[(size_t)NN * 16];  // dinv * h1
__device__ uint2  g_tb1[(size_t)NN * 16];
__device__ uint2  g_tb1s[(size_t)NN * 16];
__device__ uint2  g_tb2[(size_t)NN * 16];
__device__ uint2  g_h2[(size_t)NN * 16];   // fp16 pool input
__device__ float  g_gsum[NG * DH];

// ---------------- fp16 pack/unpack ----------------
__device__ __forceinline__ float4 ld_h4(const uint2* p) {
    uint2 u = *p;
    __half2 h0 = *reinterpret_cast<__half2*>(&u.x);
    __half2 h1 = *reinterpret_cast<__half2*>(&u.y);
    float2 f0 = __half22float2(h0), f1 = __half22float2(h1);
    return make_float4(f0.x, f0.y, f1.x, f1.y);
}
__device__ __forceinline__ uint2 st_h4(float4 v) {
    __half2 h0 = __floats2half2_rn(v.x, v.y);
    __half2 h1 = __floats2half2_rn(v.z, v.w);
    uint2 u;
    u.x = *reinterpret_cast<unsigned*>(&h0);
    u.y = *reinterpret_cast<unsigned*>(&h1);
    return u;
}

// ---------------- dtype probe (must finish before the stream fork) ----------------
__global__ void k_detect(const int* __restrict__ ei_raw, const int* __restrict__ batch_raw) {
    __shared__ int s_ei, s_b;
    int t = threadIdx.x;
    if (t == 0) { s_ei = 0; s_b = 0; }
    __syncthreads();
    int acc_e = 0, acc_b = 0;
    for (int k = t; k < 4096; k += blockDim.x) acc_e |= ei_raw[2 * k + 1];
    for (int k = t; k < 4096; k += blockDim.x) acc_b |= batch_raw[2 * k + 1];
    atomicOr(&s_ei, acc_e);
    atomicOr(&s_b, acc_b);
    __syncthreads();
    if (t == 0) {
        g_flags[0] = (s_ei == 0) ? 1 : 0;
        g_flags[1] = (s_b == 0) ? 1 : 0;
    }
}

// ---------------- prep (main stream) ----------------
__global__ void k_zero_small() {
    int i = blockIdx.x * blockDim.x + threadIdx.x;
    if (i < NN) { g_deg[i] = 0.f; g_indeg[i] = 0; g_fill[i] = 0; }
    if (i < NG * DH) g_gsum[i] = 0.f;
    if (i == 0) g_alloc = 0;
}

__global__ void k_deg_prep(const void* __restrict__ ei_raw) {
    int t = blockIdx.x * blockDim.x + threadIdx.x;
    int e = t * 2;
    if (e >= NE) return;
    int s0, s1, d0, d1;
    if (g_flags[0]) {
        longlong2 sp = ((const longlong2*)ei_raw)[t];
        longlong2 dp = ((const longlong2*)((const long long*)ei_raw + NE))[t];
        s0 = (int)sp.x; s1 = (int)sp.y;
        d0 = (int)dp.x; d1 = (int)dp.y;
    } else {
        int2 sp = ((const int2*)ei_raw)[t];
        int2 dp = ((const int2*)((const int*)ei_raw + NE))[t];
        s0 = sp.x; s1 = sp.y;
        d0 = dp.x; d1 = dp.y;
    }
    s0 = min(max(s0, 0), NN - 1); s1 = min(max(s1, 0), NN - 1);
    d0 = min(max(d0, 0), NN - 1); d1 = min(max(d1, 0), NN - 1);
    atomicAdd(&g_deg[s0], 1.0f);
    atomicAdd(&g_deg[s1], 1.0f);
    atomicAdd(&g_indeg[d0], 1);
    atomicAdd(&g_indeg[d1], 1);
}

// dinv + CSR row allocation (warp-scan, one atomicAdd per warp)
__global__ void k_alloc() {
    int i = blockIdx.x * blockDim.x + threadIdx.x;
    int lane = threadIdx.x & 31;
    if (i < NN) {
        float d = g_deg[i];
        g_dinv[i] = (d > 0.f) ? rsqrtf(d) : 0.f;
    }
    int v = (i < NN) ? g_indeg[i] : 0;
    int s = v;
#pragma unroll
    for (int o = 1; o < 32; o <<= 1) {
        int t = __shfl_up_sync(0xFFFFFFFF, s, o);
        if (lane >= o) s += t;
    }
    int total = __shfl_sync(0xFFFFFFFF, s, 31);
    int base = 0;
    if (lane == 31) base = atomicAdd(&g_alloc, total);
    base = __shfl_sync(0xFFFFFFFF, base, 31);
    if (i < NN) g_rowstart[i] = base + s - v;
}

// fill CSR (src only), 2 edges/thread, re-decoding edge_index (L2-hot)
__global__ void k_fill(const void* __restrict__ ei_raw) {
    int t = blockIdx.x * blockDim.x + threadIdx.x;
    int e = t * 2;
    if (e >= NE) return;
    int s0, s1, d0, d1;
    if (g_flags[0]) {
        longlong2 sp = ((const longlong2*)ei_raw)[t];
        longlong2 dp = ((const longlong2*)((const long long*)ei_raw + NE))[t];
        s0 = (int)sp.x; s1 = (int)sp.y;
        d0 = (int)dp.x; d1 = (int)dp.y;
    } else {
        int2 sp = ((const int2*)ei_raw)[t];
        int2 dp = ((const int2*)((const int*)ei_raw + NE))[t];
        s0 = sp.x; s1 = sp.y;
        d0 = dp.x; d1 = dp.y;
    }
    s0 = min(max(s0, 0), NN - 1); s1 = min(max(s1, 0), NN - 1);
    d0 = min(max(d0, 0), NN - 1); d1 = min(max(d1, 0), NN - 1);
    int p0 = atomicAdd(&g_fill[d0], 1);
    g_csri[g_rowstart[d0] + p0] = s0;
    int p1 = atomicAdd(&g_fill[d1], 1);
    g_csri[g_rowstart[d1] + p1] = s1;
}

// ---------------- prep (side stream) ----------------
__global__ void k_batch_prep(const void* __restrict__ batch_raw) {
    int i = blockIdx.x * blockDim.x + threadIdx.x;
    if (i < NG) { g_gstart[i] = 0; g_gend[i] = 0; }
    if (i >= NN) return;
    int b;
    if (g_flags[1]) b = (int)((const long long*)batch_raw)[i];
    else            b = ((const int*)batch_raw)[i];
    g_batch[i] = min(max(b, 0), NG - 1);
}

__global__ void k_bounds() {
    int i = blockIdx.x * blockDim.x + threadIdx.x;
    if (i >= NN) return;
    int b = g_batch[i];
    if (i == 0 || g_batch[i - 1] != b) g_gstart[b] = i;
    if (i == NN - 1 || g_batch[i + 1] != b) g_gend[b] = i + 1;
}

// build Wcat = [W0-W2 | W1 | W2] (128 x 192)
__global__ void k_wcat(const float* __restrict__ W1) {
    int t = blockIdx.x * blockDim.x + threadIdx.x;
    if (t >= DIN * 192) return;
    int i = t / 192, o = t % 192;
    float v;
    if (o < 64)       v = W1[i * 64 + o] - W1[2 * 8192 + i * 64 + o];
    else if (o < 128) v = W1[8192 + i * 64 + (o - 64)];
    else              v = W1[2 * 8192 + i * 64 + (o - 128)];
    g_wcat[t] = v;
}

// ---------------- tensor-core GEMM 1: P = x @ Wcat ----------------
__global__ void k_gemm_p(const float4* __restrict__ A4) {
    __shared__ __align__(32) __half sA[128 * 40];
    __shared__ __align__(32) __half sB[32 * 72];
    __shared__ __align__(32) float  sC[128 * 64];
    const int tid = threadIdx.x;
    const int m0 = blockIdx.x * 128;
    const int n0 = blockIdx.y * 64;
    const int wid = tid >> 5;
    const int wm = wid & 3, wn = wid >> 2;

    wmma::fragment<wmma::accumulator, 16, 16, 16, float> c[2][2];
#pragma unroll
    for (int i = 0; i < 2; i++)
#pragma unroll
        for (int j = 0; j < 2; j++) wmma::fill_fragment(c[i][j], 0.f);

    const int arow = tid >> 1, aseg = tid & 1;
    const int brow = tid >> 3, bc8 = (tid & 7) * 8;

    for (int k0 = 0; k0 < 128; k0 += 32) {
        __syncthreads();
        {
            int gm = m0 + arow;
            uint2* dst = reinterpret_cast<uint2*>(sA) + arow * 10 + aseg * 4;
            if (gm < NN) {
                const float4* src = A4 + (size_t)gm * 32 + (k0 >> 2) + aseg * 4;
#pragma unroll
                for (int q = 0; q < 4; q++) dst[q] = st_h4(src[q]);
            } else {
                uint2 z = make_uint2(0u, 0u);
#pragma unroll
                for (int q = 0; q < 4; q++) dst[q] = z;
            }
        }
        {
            const float4* src = (const float4*)(g_wcat + (size_t)(k0 + brow) * 192 + n0 + bc8);
            uint2* dst = reinterpret_cast<uint2*>(sB) + brow * 18 + (tid & 7) * 2;
            dst[0] = st_h4(src[0]);
            dst[1] = st_h4(src[1]);
        }
        __syncthreads();
#pragma unroll
        for (int kk = 0; kk < 32; kk += 16) {
            wmma::fragment<wmma::matrix_a, 16, 16, 16, __half, wmma::row_major> a[2];
            wmma::fragment<wmma::matrix_b, 16, 16, 16, __half, wmma::row_major> b[2];
#pragma unroll
            for (int i = 0; i < 2; i++)
                wmma::load_matrix_sync(a[i], sA + (wm * 32 + i * 16) * 40 + kk, 40);
#pragma unroll
            for (int j = 0; j < 2; j++)
                wmma::load_matrix_sync(b[j], sB + kk * 72 + wn * 32 + j * 16, 72);
#pragma unroll
            for (int i = 0; i < 2; i++)
#pragma unroll
                for (int j = 0; j < 2; j++) wmma::mma_sync(c[i][j], a[i], b[j], c[i][j]);
        }
    }
#pragma unroll
    for (int i = 0; i < 2; i++)
#pragma unroll
        for (int j = 0; j < 2; j++)
            wmma::store_matrix_sync(sC + (wm * 32 + i * 16) * 64 + wn * 32 + j * 16,
                                    c[i][j], 64, wmma::mem_row_major);
    __syncthreads();
    {
        int row = tid >> 1, seg = tid & 1;
        int gm = m0 + row;
        if (gm < NN) {
            const float* src = sC + row * 64 + seg * 32;
            uint2* dst = g_P + (size_t)gm * 48 + (n0 >> 2) + seg * 8;
#pragma unroll
            for (int q = 0; q < 8; q++)
                dst[q] = st_h4(make_float4(src[q * 4], src[q * 4 + 1], src[q * 4 + 2], src[q * 4 + 3]));
        }
    }
}

// ---------------- gathers (weight-factorized; fp16 in, fp32 accumulate) ----------------
// gather 1: sum2 = sum dinv[s]*P2[s]; Rsc = dv*P1 - 2*dv^2*sum2  (= dinv*(P1+2*Lhat(P2)))
__global__ void k_gatherS() {
    int g = blockIdx.x * blockDim.x + threadIdx.x;
    int node = g >> 4;
    if (node >= NN) return;
    int lane = g & 15;
    int start = g_rowstart[node];
    int cnt = g_indeg[node];
    float4 sum = make_float4(0.f, 0.f, 0.f, 0.f);
    const int* cs = g_csri + start;
    int j = 0;
    for (; j + 8 <= cnt; j += 8) {
        int e[8];
        float ds[8];
        float4 v[8];
#pragma unroll
        for (int u = 0; u < 8; u++) e[u] = cs[j + u];
#pragma unroll
        for (int u = 0; u < 8; u++) { ds[u] = g_dinv[e[u]]; v[u] = ld_h4(g_P + (size_t)e[u] * 48 + 32 + lane); }
#pragma unroll
        for (int u = 0; u < 8; u++) {
            sum.x += ds[u] * v[u].x; sum.y += ds[u] * v[u].y;
            sum.z += ds[u] * v[u].z; sum.w += ds[u] * v[u].w;
        }
    }
    for (; j < cnt; j++) {
        int e0 = cs[j];
        float d0 = g_dinv[e0];
        float4 v0 = ld_h4(g_P + (size_t)e0 * 48 + 32 + lane);
        sum.x += d0 * v0.x; sum.y += d0 * v0.y; sum.z += d0 * v0.z; sum.w += d0 * v0.w;
    }
    float dv = g_dinv[node];
    float m = -2.f * dv * dv;
    float4 p1 = ld_h4(g_P + (size_t)node * 48 + 16 + lane);
    g_Rsc[(size_t)node * 16 + lane] = st_h4(make_float4(
        dv * p1.x + m * sum.x, dv * p1.y + m * sum.y,
        dv * p1.z + m * sum.z, dv * p1.w + m * sum.w));
}

// gather 2: h1 = relu(P0 + b - dv*sum(Rsc[s])); store h1 and h1s = dv*h1
__global__ void k_combine64(const float* __restrict__ b1) {
    int g = blockIdx.x * blockDim.x + threadIdx.x;
    int node = g >> 4;
    if (node >= NN) return;
    int lane = g & 15;
    int start = g_rowstart[node];
    int cnt = g_indeg[node];
    float4 sum = make_float4(0.f, 0.f, 0.f, 0.f);
    const int* cs = g_csri + start;
    int j = 0;
    for (; j + 8 <= cnt; j += 8) {
        int e[8];
        float4 v[8];
#pragma unroll
        for (int u = 0; u < 8; u++) e[u] = cs[j + u];
#pragma unroll
        for (int u = 0; u < 8; u++) v[u] = ld_h4(g_Rsc + (size_t)e[u] * 16 + lane);
#pragma unroll
        for (int u = 0; u < 8; u++) {
            sum.x += v[u].x; sum.y += v[u].y; sum.z += v[u].z; sum.w += v[u].w;
        }
    }
    for (; j < cnt; j++) {
        int e0 = cs[j];
        float4 v0 = ld_h4(g_Rsc + (size_t)e0 * 16 + lane);
        sum.x += v0.x; sum.y += v0.y; sum.z += v0.z; sum.w += v0.w;
    }
    float dv = g_dinv[node];
    float4 p0 = ld_h4(g_P + (size_t)node * 48 + lane);
    float4 bb = *(const float4*)(b1 + lane * 4);
    float4 acc;
    acc.x = fmaxf(p0.x + bb.x - dv * sum.x, 0.f);
    acc.y = fmaxf(p0.y + bb.y - dv * sum.y, 0.f);
    acc.z = fmaxf(p0.z + bb.z - dv * sum.z, 0.f);
    acc.w = fmaxf(p0.w + bb.w - dv * sum.w, 0.f);
    g_h1[(size_t)node * 16 + lane] = st_h4(acc);
    g_h1s[(size_t)node * 16 + lane] =
        st_h4(make_float4(dv * acc.x, dv * acc.y, dv * acc.z, dv * acc.w));
}

// generic D=64 factorized gather:
// val = mul*dv*sum(in[s]) - (subsrc? subsrc[node]:0); out = val; outs = dv*val (optional)
__global__ void k_gather64(const uint2* __restrict__ in, uint2* __restrict__ out,
                           uint2* __restrict__ outs, const uint2* __restrict__ subsrc,
                           float mul) {
    int g = blockIdx.x * blockDim.x + threadIdx.x;
    int node = g >> 4;
    if (node >= NN) return;
    int lane = g & 15;
    int start = g_rowstart[node];
    int cnt = g_indeg[node];
    float4 sum = make_float4(0.f, 0.f, 0.f, 0.f);
    const int* cs = g_csri + start;
    int j = 0;
    for (; j + 8 <= cnt; j += 8) {
        int e[8];
        float4 v[8];
#pragma unroll
        for (int u = 0; u < 8; u++) e[u] = cs[j + u];
#pragma unroll
        for (int u = 0; u < 8; u++) v[u] = ld_h4(in + (size_t)e[u] * 16 + lane);
#pragma unroll
        for (int u = 0; u < 8; u++) {
            sum.x += v[u].x; sum.y += v[u].y; sum.z += v[u].z; sum.w += v[u].w;
        }
    }
    for (; j < cnt; j++) {
        int e0 = cs[j];
        float4 v0 = ld_h4(in + (size_t)e0 * 16 + lane);
        sum.x += v0.x; sum.y += v0.y; sum.z += v0.z; sum.w += v0.w;
    }
    float dv = g_dinv[node];
    float m = mul * dv;
    float4 val = make_float4(m * sum.x, m * sum.y, m * sum.z, m * sum.w);
    if (subsrc) {
        float4 t = ld_h4(subsrc + (size_t)node * 16 + lane);
        val.x -= t.x; val.y -= t.y; val.z -= t.z; val.w -= t.w;
    }
    out[(size_t)node * 16 + lane] = st_h4(val);
    if (outs)
        outs[(size_t)node * 16 + lane] =
            st_h4(make_float4(dv * val.x, dv * val.y, dv * val.z, dv * val.w));
}

// ---------------- tensor-core GEMM 2: h2 = relu([h1|tb1|tb2] @ W2 + b2), fp16 out ----------------
__global__ void k_gemm3(const float* __restrict__ W, const float* __restrict__ bias) {
    __shared__ __align__(32) __half sA[128 * 40];
    __shared__ __align__(32) __half sB[32 * 72];
    __shared__ __align__(32) float  sC[128 * 64];
    const int tid = threadIdx.x;
    const int m0 = blockIdx.x * 128;
    const int wid = tid >> 5;
    const int wm = wid & 3, wn = wid >> 2;

    wmma::fragment<wmma::accumulator, 16, 16, 16, float> c[2][2];
#pragma unroll
    for (int i = 0; i < 2; i++)
#pragma unroll
        for (int j = 0; j < 2; j++) wmma::fill_fragment(c[i][j], 0.f);

    const int arow = tid >> 1, aseg = tid & 1;
    const int brow = tid >> 3, bc8 = (tid & 7) * 8;

    for (int k0 = 0; k0 < 192; k0 += 32) {
        const uint2* Asrc = (k0 < 64) ? g_h1 : (k0 < 128 ? g_tb1 : g_tb2);
        const int koff = (k0 & 63) >> 2;
        __syncthreads();
        {
            int gm = m0 + arow;
            uint2* dst = reinterpret_cast<uint2*>(sA) + arow * 10 + aseg * 4;
            if (gm < NN) {
                const uint2* src = Asrc + (size_t)gm * 16 + koff + aseg * 4;
#pragma unroll
                for (int q = 0; q < 4; q++) dst[q] = src[q];
            } else {
                uint2 z = make_uint2(0u, 0u);
#pragma unroll
                for (int q = 0; q < 4; q++) dst[q] = z;
            }
        }
        {
            const float4* src = (const float4*)(W + (size_t)(k0 + brow) * 64 + bc8);
            uint2* dst = reinterpret_cast<uint2*>(sB) + brow * 18 + (tid & 7) * 2;
            dst[0] = st_h4(src[0]);
            dst[1] = st_h4(src[1]);
        }
        __syncthreads();
#pragma unroll
        for (int kk = 0; kk < 32; kk += 16) {
            wmma::fragment<wmma::matrix_a, 16, 16, 16, __half, wmma::row_major> a[2];
            wmma::fragment<wmma::matrix_b, 16, 16, 16, __half, wmma::row_major> b[2];
#pragma unroll
            for (int i = 0; i < 2; i++)
                wmma::load_matrix_sync(a[i], sA + (wm * 32 + i * 16) * 40 + kk, 40);
#pragma unroll
            for (int j = 0; j < 2; j++)
                wmma::load_matrix_sync(b[j], sB + kk * 72 + wn * 32 + j * 16, 72);
#pragma unroll
            for (int i = 0; i < 2; i++)
#pragma unroll
                for (int j = 0; j < 2; j++) wmma::mma_sync(c[i][j], a[i], b[j], c[i][j]);
        }
    }
#pragma unroll
    for (int i = 0; i < 2; i++)
#pragma unroll
        for (int j = 0; j < 2; j++)
            wmma::store_matrix_sync(sC + (wm * 32 + i * 16) * 64 + wn * 32 + j * 16,
                                    c[i][j], 64, wmma::mem_row_major);
    __syncthreads();
    {
        int row = tid >> 1, seg = tid & 1;
        int gm = m0 + row;
        if (gm < NN) {
            const float* src = sC + row * 64 + seg * 32;
#pragma unroll
            for (int q = 0; q < 8; q++) {
                float4 bb = *(const float4*)(bias + seg * 32 + q * 4);
                float4 o;
                o.x = fmaxf(src[q * 4 + 0] + bb.x, 0.f);
                o.y = fmaxf(src[q * 4 + 1] + bb.y, 0.f);
                o.z = fmaxf(src[q * 4 + 2] + bb.z, 0.f);
                o.w = fmaxf(src[q * 4 + 3] + bb.w, 0.f);
                g_h2[(size_t)gm * 16 + seg * 8 + q] = st_h4(o);
            }
        }
    }
}

// ---------------- pooling + FC ----------------
__global__ void k_pool() {
    int col4 = threadIdx.x & 15;
    int sub = threadIdx.x >> 4;
    int n0 = blockIdx.x * 512 + sub * 32;
    float4 acc = make_float4(0.f, 0.f, 0.f, 0.f);
    int cur = -1;
    for (int k = 0; k < 32; k++) {
        int n = n0 + k;
        if (n >= NN) break;
        int gph = g_batch[n];
        if (gph != cur) {
            if (cur >= 0) {
                atomicAdd(&g_gsum[cur * 64 + col4 * 4 + 0], acc.x);
                atomicAdd(&g_gsum[cur * 64 + col4 * 4 + 1], acc.y);
                atomicAdd(&g_gsum[cur * 64 + col4 * 4 + 2], acc.z);
                atomicAdd(&g_gsum[cur * 64 + col4 * 4 + 3], acc.w);
            }
            cur = gph;
            acc = make_float4(0.f, 0.f, 0.f, 0.f);
        }
        float4 v = ld_h4(g_h2 + (size_t)n * 16 + col4);
        acc.x += v.x; acc.y += v.y; acc.z += v.z; acc.w += v.w;
    }
    if (cur >= 0) {
        atomicAdd(&g_gsum[cur * 64 + col4 * 4 + 0], acc.x);
        atomicAdd(&g_gsum[cur * 64 + col4 * 4 + 1], acc.y);
        atomicAdd(&g_gsum[cur * 64 + col4 * 4 + 2], acc.z);
        atomicAdd(&g_gsum[cur * 64 + col4 * 4 + 3], acc.w);
    }
}

__global__ void k_final(const float* __restrict__ Wfc, const float* __restrict__ bfc,
                        float* __restrict__ out) {
    int gph = threadIdx.x;
    if (gph < NG) {
        float c = fmaxf((float)(g_gend[gph] - g_gstart[gph]), 1.0f);
        float s = 0.f;
#pragma unroll
        for (int o = 0; o < 64; o++) s += g_gsum[gph * 64 + o] * Wfc[o];
        out[gph] = s / c + bfc[0];
    }
}

// ---------------- launch ----------------
extern "C" void kernel_launch(void* const* d_in, const int* in_sizes, int n_in,
                              void* d_out, int out_size) {
    const float *x = nullptr, *W1 = nullptr, *b1 = nullptr, *W2 = nullptr,
                *b2 = nullptr, *Wfc = nullptr, *bfc = nullptr;
    const void *ei = nullptr, *batch = nullptr;
    int idx64[3] = {-1, -1, -1};
    int n64 = 0, idxW2 = -1;
    for (int i = 0; i < n_in; i++) {
        int s = in_sizes[i];
        switch (s) {
            case 12800000: x = (const float*)d_in[i]; break;
            case 6400000:  ei = d_in[i]; break;
            case 100000:   batch = d_in[i]; break;
            case 24576:    W1 = (const float*)d_in[i]; break;
            case 12288:    W2 = (const float*)d_in[i]; idxW2 = i; break;
            case 1:        bfc = (const float*)d_in[i]; break;
            case 64:       if (n64 < 3) idx64[n64++] = i; break;
            default: break;
        }
    }
    if (n64 == 3) {
        if (idx64[0] < idxW2) {
            b1 = (const float*)d_in[idx64[0]];
            b2 = (const float*)d_in[idx64[1]];
            Wfc = (const float*)d_in[idx64[2]];
        } else {
            Wfc = (const float*)d_in[idx64[0]];
            b1 = (const float*)d_in[idx64[1]];
            b2 = (const float*)d_in[idx64[2]];
        }
    }
    float* out = (float*)d_out;

    uint2 *h1, *h1s, *tb1, *tb1s, *tb2;
    cudaGetSymbolAddress((void**)&h1, g_h1);
    cudaGetSymbolAddress((void**)&h1s, g_h1s);
    cudaGetSymbolAddress((void**)&tb1, g_tb1);
    cudaGetSymbolAddress((void**)&tb1s, g_tb1s);
    cudaGetSymbolAddress((void**)&tb2, g_tb2);

    static cudaStream_t s_side = nullptr;
    static cudaEvent_t s_fork = nullptr, s_join = nullptr;
    if (!s_side) {
        cudaStreamCreateWithFlags(&s_side, cudaStreamNonBlocking);
        cudaEventCreateWithFlags(&s_fork, cudaEventDisableTiming);
        cudaEventCreateWithFlags(&s_join, cudaEventDisableTiming);
    }

    const int TB = 256;

    // detect FIRST (both streams read g_flags), then fork
    k_detect<<<1, 256>>>((const int*)ei, (const int*)batch);
    cudaEventRecord(s_fork, 0);
    cudaStreamWaitEvent(s_side, s_fork, 0);

    // side stream: layer-1 GEMM + batch bookkeeping
    {
        dim3 gp((NN + 127) / 128, 3);
        k_wcat<<<(DIN * 192 + TB - 1) / TB, TB, 0, s_side>>>(W1);
        k_gemm_p<<<gp, TB, 0, s_side>>>((const float4*)x);
        k_batch_prep<<<(NN + TB - 1) / TB, TB, 0, s_side>>>(batch);
        k_bounds<<<(NN + TB - 1) / TB, TB, 0, s_side>>>();
        cudaEventRecord(s_join, s_side);
    }

    // main stream: CSR build
    k_zero_small<<<(NN + TB - 1) / TB, TB>>>();
    k_deg_prep<<<(NE / 2 + TB - 1) / TB, TB>>>(ei);
    k_alloc<<<(NN + TB - 1) / TB, TB>>>();
    k_fill<<<(NE / 2 + TB - 1) / TB, TB>>>(ei);

    cudaStreamWaitEvent(0, s_join, 0);

    // layer 1: Rsc = dinv*(P1 + 2*Lhat(P2)); h1 = relu(P0 + Lhat-combine + b1)
    {
        int g64 = (NN * 16 + TB - 1) / TB;
        k_gatherS<<<g64, TB>>>();
        k_combine64<<<g64, TB>>>(b1);
    }

    // layer 2
    {
        int g64 = (NN * 16 + TB - 1) / TB;
        k_gather64<<<g64, TB>>>(h1s, tb1, tb1s, nullptr, -1.0f);
        k_gather64<<<g64, TB>>>(tb1s, tb2, nullptr, h1, -2.0f);
        k_gemm3<<<(NN + 127) / 128, TB>>>(W2, b2);
    }

    // mean pool per graph + FC
    k_pool<<<(NN + 511) / 512, TB>>>();
    k_final<<<1, TB>>>(Wfc, bfc, out);
}